// round 2
// baseline (speedup 1.0000x reference)
#include <cuda_runtime.h>
#include <math.h>

// Problem constants
#define BB   4
#define HH   8
#define SS   2048
#define DM   512
#define DQ   64

// ---------------- device scratch (allocation-free rule: __device__ globals) ----
__device__ float g_Wq[DM * DM];
__device__ float g_Wk[DM * DM];
__device__ float g_Wv[DM * DM];
__device__ float g_Wo[DM * DM];
__device__ float g_q[BB * SS * DM];   // [b, s, h, dq]  (= [8192, 512])
__device__ float g_k[BB * SS * DM];   // [b, s, h, dq]
__device__ float g_v[BB * SS * DM];   // [b, s, h, dq]
__device__ float g_h[BB * SS * DM];   // [b, h, s, dq]  (== concat view, flat)

// ---------------- weight reorder ---------------------------------------------
// g_Wq[d*512 + h*64 + q] = Q[h, d, q]; g_Wo[k*512 + n] = Wout[n, k]
__global__ void prep_weights(const float* __restrict__ Qw,
                             const float* __restrict__ Kw,
                             const float* __restrict__ Vw,
                             const float* __restrict__ Wout) {
    int i = blockIdx.x * 256 + threadIdx.x;
    if (i >= DM * DM) return;
    int d = i >> 9;
    int n = i & 511;
    int h = n >> 6;
    int q = n & 63;
    int src = (h * DM + d) * DQ + q;
    g_Wq[i] = Qw[src];
    g_Wk[i] = Kw[src];
    g_Wv[i] = Vw[src];
    g_Wo[i] = Wout[n * DM + d];
}

// ---------------- SGEMM: C[M,N] = A[M,K] @ B[K,N], fp32 ----------------------
// 128x128 block tile, BK=16, 256 threads, 8x8 per-thread microtile.
__global__ __launch_bounds__(256) void sgemm128(const float* __restrict__ A,
                                                const float* __restrict__ B,
                                                float* __restrict__ C,
                                                int M, int N, int K) {
    __shared__ float As[16 * 132];  // [k][m], padded stride 132
    __shared__ float Bs[16 * 128];  // [k][n]

    const int tid = threadIdx.x;
    const int tx = tid & 15;
    const int ty = tid >> 4;
    const int row0 = blockIdx.y * 128;
    const int col0 = blockIdx.x * 128;

    const float* gA = A + (size_t)row0 * K;
    const float* gB = B + col0;

    float acc[8][8];
#pragma unroll
    for (int i = 0; i < 8; i++)
#pragma unroll
        for (int j = 0; j < 8; j++) acc[i][j] = 0.f;

    for (int kt = 0; kt < K; kt += 16) {
        // Load A tile 128x16 (transpose into As[k][m])
#pragma unroll
        for (int it = 0; it < 2; it++) {
            int f = tid + it * 256;          // 512 float4s
            int r = f >> 2;
            int kq = (f & 3) * 4;
            float4 va = *(const float4*)(gA + (size_t)r * K + kt + kq);
            As[(kq + 0) * 132 + r] = va.x;
            As[(kq + 1) * 132 + r] = va.y;
            As[(kq + 2) * 132 + r] = va.z;
            As[(kq + 3) * 132 + r] = va.w;
        }
        // Load B tile 16x128 (direct)
#pragma unroll
        for (int it = 0; it < 2; it++) {
            int f = tid + it * 256;
            int kr = f >> 5;
            int n4 = (f & 31) * 4;
            *(float4*)(Bs + kr * 128 + n4) =
                *(const float4*)(gB + (size_t)(kt + kr) * N + n4);
        }
        __syncthreads();

#pragma unroll
        for (int k = 0; k < 16; k++) {
            float a[8], b[8];
            float4 t0 = *(const float4*)(As + k * 132 + ty * 4);
            float4 t1 = *(const float4*)(As + k * 132 + ty * 4 + 64);
            a[0] = t0.x; a[1] = t0.y; a[2] = t0.z; a[3] = t0.w;
            a[4] = t1.x; a[5] = t1.y; a[6] = t1.z; a[7] = t1.w;
            float4 u0 = *(const float4*)(Bs + k * 128 + tx * 4);
            float4 u1 = *(const float4*)(Bs + k * 128 + tx * 4 + 64);
            b[0] = u0.x; b[1] = u0.y; b[2] = u0.z; b[3] = u0.w;
            b[4] = u1.x; b[5] = u1.y; b[6] = u1.z; b[7] = u1.w;
#pragma unroll
            for (int i = 0; i < 8; i++)
#pragma unroll
                for (int j = 0; j < 8; j++) acc[i][j] += a[i] * b[j];
        }
        __syncthreads();
    }

    // Epilogue
#pragma unroll
    for (int i = 0; i < 8; i++) {
        int r = row0 + ((i < 4) ? (ty * 4 + i) : (ty * 4 + 64 + (i - 4)));
        float4 v0 = make_float4(acc[i][0], acc[i][1], acc[i][2], acc[i][3]);
        float4 v1 = make_float4(acc[i][4], acc[i][5], acc[i][6], acc[i][7]);
        *(float4*)(C + (size_t)r * N + col0 + tx * 4) = v0;
        *(float4*)(C + (size_t)r * N + col0 + tx * 4 + 64) = v1;
    }
}

// ---------------- Flash attention, fp32, 64x64 tiles, d=64 -------------------
// q/k/v in [b,s,h,dq]; output heads in [b,h,s,dq] (contiguous == concat view).
#define FLD 68   // padded smem row stride (floats)

__global__ __launch_bounds__(256) void flash64(const float* __restrict__ qp,
                                               const float* __restrict__ kp,
                                               const float* __restrict__ vp,
                                               float* __restrict__ op) {
    extern __shared__ float sm[];
    float* Qs = sm;                 // [row][d]
    float* Ks = sm + 64 * FLD;      // [key][d]
    float* Vt = sm + 2 * 64 * FLD;  // [d][key]   (V transposed)
    float* Ps = sm + 3 * 64 * FLD;  // [row][key]

    const int tid = threadIdx.x;
    const int tx = tid & 15;
    const int ty = tid >> 4;
    const int r0 = ty * 4;

    const int b = blockIdx.z;
    const int h = blockIdx.y;
    const int s0 = blockIdx.x * 64;

    // Load Q tile (rows s0..s0+63, stride H*DQ=512 in gmem)
    const float* qbase = qp + (((size_t)(b * SS + s0)) * HH + h) * DQ;
#pragma unroll
    for (int it = 0; it < 4; it++) {
        int f = tid + it * 256;     // 1024 float4s
        int r = f >> 4;
        int d4 = (f & 15) * 4;
        float4 v = *(const float4*)(qbase + (size_t)r * DM + d4);
        Qs[r * FLD + d4 + 0] = v.x;
        Qs[r * FLD + d4 + 1] = v.y;
        Qs[r * FLD + d4 + 2] = v.z;
        Qs[r * FLD + d4 + 3] = v.w;
    }

    float m_r[4], l_r[4], o[4][4];
#pragma unroll
    for (int i = 0; i < 4; i++) {
        m_r[i] = -INFINITY;
        l_r[i] = 0.f;
#pragma unroll
        for (int j = 0; j < 4; j++) o[i][j] = 0.f;
    }

    for (int t0 = 0; t0 < SS; t0 += 64) {
        __syncthreads();  // previous P@V done before overwriting Ks/Vt

        const float* kbase = kp + (((size_t)(b * SS + t0)) * HH + h) * DQ;
        const float* vbase = vp + (((size_t)(b * SS + t0)) * HH + h) * DQ;
#pragma unroll
        for (int it = 0; it < 4; it++) {
            int f = tid + it * 256;
            int r = f >> 4;
            int d4 = (f & 15) * 4;
            float4 kv = *(const float4*)(kbase + (size_t)r * DM + d4);
            Ks[r * FLD + d4 + 0] = kv.x;
            Ks[r * FLD + d4 + 1] = kv.y;
            Ks[r * FLD + d4 + 2] = kv.z;
            Ks[r * FLD + d4 + 3] = kv.w;
            float4 vv = *(const float4*)(vbase + (size_t)r * DM + d4);
            Vt[(d4 + 0) * FLD + r] = vv.x;
            Vt[(d4 + 1) * FLD + r] = vv.y;
            Vt[(d4 + 2) * FLD + r] = vv.z;
            Vt[(d4 + 3) * FLD + r] = vv.w;
        }
        __syncthreads();

        // S = Q @ K^T (thread covers rows r0..r0+3, cols tx+16*j)
        float s[4][4];
#pragma unroll
        for (int i = 0; i < 4; i++)
#pragma unroll
            for (int j = 0; j < 4; j++) s[i][j] = 0.f;

#pragma unroll
        for (int kk = 0; kk < 64; kk += 4) {
            float4 qf[4], kf[4];
#pragma unroll
            for (int i = 0; i < 4; i++)
                qf[i] = *(const float4*)(Qs + (r0 + i) * FLD + kk);
#pragma unroll
            for (int j = 0; j < 4; j++)
                kf[j] = *(const float4*)(Ks + (tx + 16 * j) * FLD + kk);
#pragma unroll
            for (int i = 0; i < 4; i++)
#pragma unroll
                for (int j = 0; j < 4; j++)
                    s[i][j] += qf[i].x * kf[j].x + qf[i].y * kf[j].y +
                               qf[i].z * kf[j].z + qf[i].w * kf[j].w;
        }

        // online softmax (row reductions across 16 lanes sharing a row)
#pragma unroll
        for (int i = 0; i < 4; i++) {
#pragma unroll
            for (int j = 0; j < 4; j++) s[i][j] *= 0.125f;  // 1/sqrt(64)

            float mx = fmaxf(fmaxf(s[i][0], s[i][1]), fmaxf(s[i][2], s[i][3]));
#pragma unroll
            for (int off = 8; off > 0; off >>= 1)
                mx = fmaxf(mx, __shfl_xor_sync(0xffffffffu, mx, off));

            float mnew = fmaxf(m_r[i], mx);
            float alpha = __expf(m_r[i] - mnew);
            float sum = 0.f;
#pragma unroll
            for (int j = 0; j < 4; j++) {
                float p = __expf(s[i][j] - mnew);
                s[i][j] = p;
                sum += p;
            }
#pragma unroll
            for (int off = 8; off > 0; off >>= 1)
                sum += __shfl_xor_sync(0xffffffffu, sum, off);

            l_r[i] = l_r[i] * alpha + sum;
            m_r[i] = mnew;
#pragma unroll
            for (int j = 0; j < 4; j++) o[i][j] *= alpha;
#pragma unroll
            for (int j = 0; j < 4; j++)
                Ps[(r0 + i) * FLD + tx + 16 * j] = s[i][j];
        }
        __syncthreads();

        // O += P @ V   (cols of o are d-dims tx+16*j, via transposed V)
#pragma unroll
        for (int k = 0; k < 64; k += 4) {
            float4 pf[4], vf[4];
#pragma unroll
            for (int i = 0; i < 4; i++)
                pf[i] = *(const float4*)(Ps + (r0 + i) * FLD + k);
#pragma unroll
            for (int j = 0; j < 4; j++)
                vf[j] = *(const float4*)(Vt + (tx + 16 * j) * FLD + k);
#pragma unroll
            for (int i = 0; i < 4; i++)
#pragma unroll
                for (int j = 0; j < 4; j++)
                    o[i][j] += pf[i].x * vf[j].x + pf[i].y * vf[j].y +
                               pf[i].z * vf[j].z + pf[i].w * vf[j].w;
        }
    }

    // normalize + store heads in [b,h,s,dq]
    float* obase = op + (((size_t)(b * HH + h)) * SS + s0) * DQ;
#pragma unroll
    for (int i = 0; i < 4; i++) {
        float inv = 1.f / l_r[i];
#pragma unroll
        for (int j = 0; j < 4; j++)
            obase[(size_t)(r0 + i) * DQ + tx + 16 * j] = o[i][j] * inv;
    }
}

// ---------------- launch ------------------------------------------------------
extern "C" void kernel_launch(void* const* d_in, const int* in_sizes, int n_in,
                              void* d_out, int out_size) {
    const float* xq  = (const float*)d_in[0];
    const float* xk  = (const float*)d_in[1];
    const float* xv  = (const float*)d_in[2];
    const float* Qw  = (const float*)d_in[3];
    const float* Kw  = (const float*)d_in[4];
    const float* Vw  = (const float*)d_in[5];
    const float* Wo  = (const float*)d_in[6];
    float* out = (float*)d_out;

    float *pWq, *pWk, *pWv, *pWo, *pq, *pk, *pv, *ph;
    cudaGetSymbolAddress((void**)&pWq, g_Wq);
    cudaGetSymbolAddress((void**)&pWk, g_Wk);
    cudaGetSymbolAddress((void**)&pWv, g_Wv);
    cudaGetSymbolAddress((void**)&pWo, g_Wo);
    cudaGetSymbolAddress((void**)&pq,  g_q);
    cudaGetSymbolAddress((void**)&pk,  g_k);
    cudaGetSymbolAddress((void**)&pv,  g_v);
    cudaGetSymbolAddress((void**)&ph,  g_h);

    // 1) reorder weights
    prep_weights<<<(DM * DM + 255) / 256, 256>>>(Qw, Kw, Vw, Wo);

    // 2) projections: [8192,512] @ [512,512]
    dim3 ggrid(DM / 128, (BB * SS) / 128);
    sgemm128<<<ggrid, 256>>>(xq, pWq, pq, BB * SS, DM, DM);
    sgemm128<<<ggrid, 256>>>(xk, pWk, pk, BB * SS, DM, DM);
    sgemm128<<<ggrid, 256>>>(xv, pWv, pv, BB * SS, DM, DM);

    // 3) flash attention per (b,h), 64-row query tiles
    size_t shmem = 4 * 64 * FLD * sizeof(float);  // 69632 B
    cudaFuncSetAttribute(flash64, cudaFuncAttributeMaxDynamicSharedMemorySize,
                         (int)shmem);
    flash64<<<dim3(SS / 64, HH, BB), 256, shmem>>>(pq, pk, pv, ph);

    // 4) output projection: concat (== g_h flat) @ Wout^T -> d_out
    sgemm128<<<ggrid, 256>>>(ph, pWo, out, BB * SS, DM, DM);
}

// round 4
// speedup vs baseline: 2.4023x; 2.4023x over previous
#include <cuda_runtime.h>
#include <math.h>
#include <stdint.h>

#define BB 4
#define HH 8
#define SS 2048
#define DM 512
#define DQ 64

// ---------------------------------------------------------------- tf32 utils
__device__ __forceinline__ uint32_t f2tf(float x) {
    uint32_t r;
    asm("cvt.rna.tf32.f32 %0, %1;" : "=r"(r) : "f"(x));
    return r;
}
__device__ __forceinline__ float f2tff(float x) {
    return __uint_as_float(f2tf(x));
}

// D += A(16x8) @ B(8x8), tf32 inputs, fp32 accum
__device__ __forceinline__ void mma8(float d[4], const uint32_t a[4],
                                     const uint32_t b[2]) {
    asm volatile(
        "mma.sync.aligned.m16n8k8.row.col.f32.tf32.tf32.f32 "
        "{%0,%1,%2,%3}, {%4,%5,%6,%7}, {%8,%9}, {%0,%1,%2,%3};"
        : "+f"(d[0]), "+f"(d[1]), "+f"(d[2]), "+f"(d[3])
        : "r"(a[0]), "r"(a[1]), "r"(a[2]), "r"(a[3]), "r"(b[0]), "r"(b[1]));
}

// ---------------------------------------------------------------- scratch
__device__ float g_Wq[DM * DM];
__device__ float g_Wk[DM * DM];
__device__ float g_Wv[DM * DM];
__device__ float g_q[BB * SS * DM];   // [b,s,h,dq]
__device__ float g_k[BB * SS * DM];
__device__ float g_v[BB * SS * DM];
__device__ float g_h[BB * SS * DM];   // [b,h,s,dq] == concat view (flat)

// weights transposed to [n][k] (k contiguous)
__global__ void prep_weights(const float* __restrict__ Qw,
                             const float* __restrict__ Kw,
                             const float* __restrict__ Vw) {
    int i = blockIdx.x * 256 + threadIdx.x;
    if (i >= DM * DM) return;
    int n = i >> 9;       // output feature (h*64+q)
    int d = i & 511;      // input feature
    int h = n >> 6;
    int q = n & 63;
    int src = (h * DM + d) * DQ + q;
    g_Wq[i] = Qw[src];
    g_Wk[i] = Kw[src];
    g_Wv[i] = Vw[src];
}

// ---------------------------------------------------------------- GEMM
// C[M,N] = A[M,K] @ B[N,K]^T.  128x128 CTA tile, BK=16, 256 threads (8 warps,
// warp grid 2m x 4n -> warp tile 64x32). tf32 mma.sync.
#define GLD 17   // smem row stride (floats)

__global__ __launch_bounds__(256) void gemm_mma(const float* __restrict__ A,
                                                const float* __restrict__ B,
                                                float* __restrict__ C,
                                                int M, int N, int K) {
    __shared__ float As[128 * GLD];
    __shared__ float Bs[128 * GLD];

    const int tid = threadIdx.x;
    const int lane = tid & 31;
    const int wid = tid >> 5;
    const int g = lane >> 2;
    const int t = lane & 3;
    const int wm = wid & 1;       // 0..1 -> m offset wm*64
    const int wn = wid >> 1;      // 0..3 -> n offset wn*32
    const int m0 = blockIdx.y * 128;
    const int n0 = blockIdx.x * 128;

    const float* gA = A + (size_t)m0 * K;
    const float* gB = B + (size_t)n0 * K;

    float d[4][4][4];
#pragma unroll
    for (int i = 0; i < 4; i++)
#pragma unroll
        for (int j = 0; j < 4; j++)
#pragma unroll
            for (int c = 0; c < 4; c++) d[i][j][c] = 0.f;

    for (int kt = 0; kt < K; kt += 16) {
        __syncthreads();
#pragma unroll
        for (int it = 0; it < 2; it++) {
            int f = tid + it * 256;       // 512 float4 per tile
            int r = f >> 2;
            int c4 = (f & 3) * 4;
            float4 va = *(const float4*)(gA + (size_t)r * K + kt + c4);
            As[r * GLD + c4 + 0] = f2tff(va.x);
            As[r * GLD + c4 + 1] = f2tff(va.y);
            As[r * GLD + c4 + 2] = f2tff(va.z);
            As[r * GLD + c4 + 3] = f2tff(va.w);
            float4 vb = *(const float4*)(gB + (size_t)r * K + kt + c4);
            Bs[r * GLD + c4 + 0] = f2tff(vb.x);
            Bs[r * GLD + c4 + 1] = f2tff(vb.y);
            Bs[r * GLD + c4 + 2] = f2tff(vb.z);
            Bs[r * GLD + c4 + 3] = f2tff(vb.w);
        }
        __syncthreads();

#pragma unroll
        for (int s = 0; s < 2; s++) {
            uint32_t a[4][4], b[4][2];
#pragma unroll
            for (int i = 0; i < 4; i++) {
                int rw = wm * 64 + i * 16;
                a[i][0] = __float_as_uint(As[(rw + g) * GLD + s * 8 + t]);
                a[i][1] = __float_as_uint(As[(rw + g + 8) * GLD + s * 8 + t]);
                a[i][2] = __float_as_uint(As[(rw + g) * GLD + s * 8 + t + 4]);
                a[i][3] = __float_as_uint(As[(rw + g + 8) * GLD + s * 8 + t + 4]);
            }
#pragma unroll
            for (int j = 0; j < 4; j++) {
                int rn = wn * 32 + j * 8;
                b[j][0] = __float_as_uint(Bs[(rn + g) * GLD + s * 8 + t]);
                b[j][1] = __float_as_uint(Bs[(rn + g) * GLD + s * 8 + t + 4]);
            }
#pragma unroll
            for (int i = 0; i < 4; i++)
#pragma unroll
                for (int j = 0; j < 4; j++) mma8(d[i][j], a[i], b[j]);
        }
    }

    // epilogue: float2 stores (c0,c1 adjacent cols)
#pragma unroll
    for (int i = 0; i < 4; i++) {
        int r0 = m0 + wm * 64 + i * 16 + g;
#pragma unroll
        for (int j = 0; j < 4; j++) {
            int cn = n0 + wn * 32 + j * 8 + t * 2;
            *(float2*)(C + (size_t)r0 * N + cn) = make_float2(d[i][j][0], d[i][j][1]);
            *(float2*)(C + (size_t)(r0 + 8) * N + cn) = make_float2(d[i][j][2], d[i][j][3]);
        }
    }
}

// ---------------------------------------------------------------- flash attention
// CTA = (b, h, 128 query rows). 256 threads, 8 warps; warp w owns rows w*16..+15.
// Q fragments in registers. K/V smem stride 68 (conflict-free B-frag loads),
// P smem stride 132 (conflict-free A-frag loads).
#define KS_OFF 0
#define VS_OFF (128 * 68)
#define PS_OFF (2 * 128 * 68)
#define FL_SMEM ((2 * 128 * 68 + 128 * 132) * 4)

__global__ __launch_bounds__(256) void flash_mma(const float* __restrict__ qp,
                                                 const float* __restrict__ kp,
                                                 const float* __restrict__ vp,
                                                 float* __restrict__ op) {
    extern __shared__ float sm[];
    float* Ks = sm + KS_OFF;   // [key][d]  stride 68
    float* Vs = sm + VS_OFF;   // [key][d]  stride 68
    float* Ps = sm + PS_OFF;   // [qrow][key] stride 132

    const int tid = threadIdx.x;
    const int lane = tid & 31;
    const int wid = tid >> 5;
    const int g = lane >> 2;
    const int t = lane & 3;
    const int b = blockIdx.z;
    const int h = blockIdx.y;
    const int s0 = blockIdx.x * 128;
    const int r0 = wid * 16 + g;      // this thread's query rows: r0, r0+8

    // Q fragments (row-major A frags, 8 k-steps of 8)
    const float* gq = qp + (((size_t)(b * SS + s0)) * HH + h) * DQ;
    uint32_t qa[8][4];
#pragma unroll
    for (int s = 0; s < 8; s++) {
        qa[s][0] = f2tf(gq[(size_t)r0 * DM + s * 8 + t]);
        qa[s][1] = f2tf(gq[(size_t)(r0 + 8) * DM + s * 8 + t]);
        qa[s][2] = f2tf(gq[(size_t)r0 * DM + s * 8 + t + 4]);
        qa[s][3] = f2tf(gq[(size_t)(r0 + 8) * DM + s * 8 + t + 4]);
    }

    float m0r = -INFINITY, m1r = -INFINITY, l0 = 0.f, l1 = 0.f;
    float o[8][4];
#pragma unroll
    for (int j = 0; j < 8; j++)
#pragma unroll
        for (int c = 0; c < 4; c++) o[j][c] = 0.f;

    for (int t0 = 0; t0 < SS; t0 += 128) {
        __syncthreads();  // prior tile's mma reads of Ks/Vs complete

        const float* gk = kp + (((size_t)(b * SS + t0)) * HH + h) * DQ;
        const float* gv = vp + (((size_t)(b * SS + t0)) * HH + h) * DQ;
#pragma unroll
        for (int it = 0; it < 8; it++) {
            int f = tid + it * 256;    // 2048 float4s (K then V interleaved by f)
            int r = f >> 4;
            int c4 = (f & 15) * 4;
            float4 kv = *(const float4*)(gk + (size_t)r * DM + c4);
            Ks[r * 68 + c4 + 0] = f2tff(kv.x);
            Ks[r * 68 + c4 + 1] = f2tff(kv.y);
            Ks[r * 68 + c4 + 2] = f2tff(kv.z);
            Ks[r * 68 + c4 + 3] = f2tff(kv.w);
            float4 vv = *(const float4*)(gv + (size_t)r * DM + c4);
            Vs[r * 68 + c4 + 0] = f2tff(vv.x);
            Vs[r * 68 + c4 + 1] = f2tff(vv.y);
            Vs[r * 68 + c4 + 2] = f2tff(vv.z);
            Vs[r * 68 + c4 + 3] = f2tff(vv.w);
        }
        __syncthreads();

        // S = Q @ K^T : warp tile 16 x 128 (16 n-tiles), K=64 (8 k-steps)
        float sj[16][4];
#pragma unroll
        for (int j = 0; j < 16; j++)
#pragma unroll
            for (int c = 0; c < 4; c++) sj[j][c] = 0.f;

#pragma unroll
        for (int s = 0; s < 8; s++) {
#pragma unroll
            for (int j = 0; j < 16; j++) {
                uint32_t bfr[2];
                bfr[0] = __float_as_uint(Ks[(j * 8 + g) * 68 + s * 8 + t]);
                bfr[1] = __float_as_uint(Ks[(j * 8 + g) * 68 + s * 8 + t + 4]);
                mma8(sj[j], qa[s], bfr);
            }
        }

        // online softmax (rows r0 and r0+8); scale 1/sqrt(64)=0.125
        float mx0 = -INFINITY, mx1 = -INFINITY;
#pragma unroll
        for (int j = 0; j < 16; j++) {
#pragma unroll
            for (int c = 0; c < 4; c++) sj[j][c] *= 0.125f;
            mx0 = fmaxf(mx0, fmaxf(sj[j][0], sj[j][1]));
            mx1 = fmaxf(mx1, fmaxf(sj[j][2], sj[j][3]));
        }
        mx0 = fmaxf(mx0, __shfl_xor_sync(0xffffffffu, mx0, 1));
        mx0 = fmaxf(mx0, __shfl_xor_sync(0xffffffffu, mx0, 2));
        mx1 = fmaxf(mx1, __shfl_xor_sync(0xffffffffu, mx1, 1));
        mx1 = fmaxf(mx1, __shfl_xor_sync(0xffffffffu, mx1, 2));

        float mn0 = fmaxf(m0r, mx0);
        float mn1 = fmaxf(m1r, mx1);
        float al0 = __expf(m0r - mn0);
        float al1 = __expf(m1r - mn1);
        m0r = mn0;
        m1r = mn1;

        float sum0 = 0.f, sum1 = 0.f;
#pragma unroll
        for (int j = 0; j < 16; j++) {
            float p0 = __expf(sj[j][0] - mn0);
            float p1 = __expf(sj[j][1] - mn0);
            float p2 = __expf(sj[j][2] - mn1);
            float p3 = __expf(sj[j][3] - mn1);
            sum0 += p0 + p1;
            sum1 += p2 + p3;
            int cn = j * 8 + t * 2;
            *(float2*)(Ps + (wid * 16 + g) * 132 + cn) =
                make_float2(f2tff(p0), f2tff(p1));
            *(float2*)(Ps + (wid * 16 + g + 8) * 132 + cn) =
                make_float2(f2tff(p2), f2tff(p3));
        }
        sum0 += __shfl_xor_sync(0xffffffffu, sum0, 1);
        sum0 += __shfl_xor_sync(0xffffffffu, sum0, 2);
        sum1 += __shfl_xor_sync(0xffffffffu, sum1, 1);
        sum1 += __shfl_xor_sync(0xffffffffu, sum1, 2);
        l0 = l0 * al0 + sum0;
        l1 = l1 * al1 + sum1;

#pragma unroll
        for (int j = 0; j < 8; j++) {
            o[j][0] *= al0;
            o[j][1] *= al0;
            o[j][2] *= al1;
            o[j][3] *= al1;
        }
        __syncwarp();  // P rows of this warp are read only by this warp

        // O += P @ V : A = P (16 x 128, 16 k-steps), B = V (8 n-tiles of d)
#pragma unroll
        for (int s = 0; s < 16; s++) {
            uint32_t pa[4];
            pa[0] = __float_as_uint(Ps[(wid * 16 + g) * 132 + s * 8 + t]);
            pa[1] = __float_as_uint(Ps[(wid * 16 + g + 8) * 132 + s * 8 + t]);
            pa[2] = __float_as_uint(Ps[(wid * 16 + g) * 132 + s * 8 + t + 4]);
            pa[3] = __float_as_uint(Ps[(wid * 16 + g + 8) * 132 + s * 8 + t + 4]);
#pragma unroll
            for (int j = 0; j < 8; j++) {
                uint32_t bfr[2];
                bfr[0] = __float_as_uint(Vs[(s * 8 + t) * 68 + j * 8 + g]);
                bfr[1] = __float_as_uint(Vs[(s * 8 + t + 4) * 68 + j * 8 + g]);
                mma8(o[j], pa, bfr);
            }
        }
    }

    // normalize + store heads in [b,h,s,dq]
    float inv0 = 1.f / l0;
    float inv1 = 1.f / l1;
    float* ob = op + (((size_t)(b * HH + h)) * SS + s0) * DQ;
#pragma unroll
    for (int j = 0; j < 8; j++) {
        int cn = j * 8 + t * 2;
        *(float2*)(ob + (size_t)r0 * DQ + cn) =
            make_float2(o[j][0] * inv0, o[j][1] * inv0);
        *(float2*)(ob + (size_t)(r0 + 8) * DQ + cn) =
            make_float2(o[j][2] * inv1, o[j][3] * inv1);
    }
}

// ---------------------------------------------------------------- launch
extern "C" void kernel_launch(void* const* d_in, const int* in_sizes, int n_in,
                              void* d_out, int out_size) {
    const float* xq = (const float*)d_in[0];
    const float* xk = (const float*)d_in[1];
    const float* xv = (const float*)d_in[2];
    const float* Qw = (const float*)d_in[3];
    const float* Kw = (const float*)d_in[4];
    const float* Vw = (const float*)d_in[5];
    const float* Wo = (const float*)d_in[6];
    float* out = (float*)d_out;

    float *pWq, *pWk, *pWv, *pq, *pk, *pv, *ph;
    cudaGetSymbolAddress((void**)&pWq, g_Wq);
    cudaGetSymbolAddress((void**)&pWk, g_Wk);
    cudaGetSymbolAddress((void**)&pWv, g_Wv);
    cudaGetSymbolAddress((void**)&pq, g_q);
    cudaGetSymbolAddress((void**)&pk, g_k);
    cudaGetSymbolAddress((void**)&pv, g_v);
    cudaGetSymbolAddress((void**)&ph, g_h);

    static int attr_done = 0;
    if (!attr_done) {
        cudaFuncSetAttribute(flash_mma, cudaFuncAttributeMaxDynamicSharedMemorySize,
                             FL_SMEM);
        attr_done = 1;
    }

    prep_weights<<<(DM * DM + 255) / 256, 256>>>(Qw, Kw, Vw);

    dim3 ggrid(DM / 128, (BB * SS) / 128);
    gemm_mma<<<ggrid, 256>>>(xq, pWq, pq, BB * SS, DM, DM);
    gemm_mma<<<ggrid, 256>>>(xk, pWk, pk, BB * SS, DM, DM);
    gemm_mma<<<ggrid, 256>>>(xv, pWv, pv, BB * SS, DM, DM);

    flash_mma<<<dim3(SS / 128, HH, BB), 256, FL_SMEM>>>(pq, pk, pv, ph);

    // output projection: concat (== g_h flat) @ Wout^T; Wout is [n][k] already
    gemm_mma<<<ggrid, 256>>>(ph, Wo, out, BB * SS, DM, DM);
}

// round 6
// speedup vs baseline: 2.4737x; 1.0297x over previous
#include <cuda_runtime.h>
#include <math.h>
#include <stdint.h>

#define BB 4
#define HH 8
#define SS 2048
#define DM 512
#define DQ 64

// ---------------------------------------------------------------- tf32 utils
__device__ __forceinline__ uint32_t f2tf(float x) {
    uint32_t r;
    asm("cvt.rna.tf32.f32 %0, %1;" : "=r"(r) : "f"(x));
    return r;
}
__device__ __forceinline__ float f2tff(float x) {
    return __uint_as_float(f2tf(x));
}

// D += A(16x8) @ B(8x8), tf32 inputs, fp32 accum
__device__ __forceinline__ void mma8(float d[4], const uint32_t a[4],
                                     const uint32_t b[2]) {
    asm volatile(
        "mma.sync.aligned.m16n8k8.row.col.f32.tf32.tf32.f32 "
        "{%0,%1,%2,%3}, {%4,%5,%6,%7}, {%8,%9}, {%0,%1,%2,%3};"
        : "+f"(d[0]), "+f"(d[1]), "+f"(d[2]), "+f"(d[3])
        : "r"(a[0]), "r"(a[1]), "r"(a[2]), "r"(a[3]), "r"(b[0]), "r"(b[1]));
}

// ---------------------------------------------------------------- scratch
__device__ float g_Wq[DM * DM];
__device__ float g_Wk[DM * DM];
__device__ float g_Wv[DM * DM];
__device__ float g_q[BB * SS * DM];   // [b,s,h,dq]
__device__ float g_k[BB * SS * DM];
__device__ float g_v[BB * SS * DM];
__device__ float g_h[BB * SS * DM];   // [b,h,s,dq] == concat view (flat)

__global__ void prep_weights(const float* __restrict__ Qw,
                             const float* __restrict__ Kw,
                             const float* __restrict__ Vw) {
    int i = blockIdx.x * 256 + threadIdx.x;
    if (i >= DM * DM) return;
    int n = i >> 9;
    int d = i & 511;
    int h = n >> 6;
    int q = n & 63;
    int src = (h * DM + d) * DQ + q;
    g_Wq[i] = Qw[src];
    g_Wk[i] = Kw[src];
    g_Wv[i] = Vw[src];
}

// ---------------------------------------------------------------- GEMM
// C[M,N] = A[M,K] @ B[N,K]^T. 128x128 CTA tile, BK=16, 8 warps (2m x 4n).
// Double-buffered smem; k-cols permuted within 8-groups so fragment pairs
// (t, t+4) are adjacent -> LDS.64. Stride 24 words: conflict-free.
#define GSTR 24
#define GE_TILE (128 * GSTR)            // floats per matrix per buffer
#define GE_SMEM (4 * GE_TILE * 4)       // bytes: As0 As1 Bs0 Bs1

__global__ __launch_bounds__(256, 2) void gemm_mma(const float* __restrict__ A,
                                                   const float* __restrict__ B,
                                                   float* __restrict__ C,
                                                   int M, int N, int K) {
    extern __shared__ float sg[];

    const int tid = threadIdx.x;
    const int lane = tid & 31;
    const int wid = tid >> 5;
    const int g = lane >> 2;
    const int t = lane & 3;
    const int wm = wid & 1;
    const int wn = wid >> 1;
    const int m0 = blockIdx.y * 128;
    const int n0 = blockIdx.x * 128;

    const float* gA = A + (size_t)m0 * K;
    const float* gB = B + (size_t)n0 * K;

    float d[4][4][4];
#pragma unroll
    for (int i = 0; i < 4; i++)
#pragma unroll
        for (int j = 0; j < 4; j++)
#pragma unroll
            for (int c = 0; c < 4; c++) d[i][j][c] = 0.f;

    float4 ra[2], rb[2];
    // prologue load k-tile 0
#pragma unroll
    for (int it = 0; it < 2; it++) {
        int f = tid + it * 256;
        int r = f >> 2;
        int c4 = (f & 3) * 4;
        ra[it] = *(const float4*)(gA + (size_t)r * K + c4);
        rb[it] = *(const float4*)(gB + (size_t)r * K + c4);
    }
    // store tile 0 into buffer 0 (permuted cols: k -> (k&~7) + 2*(k&3) + ((k&4)?1:0))
#pragma unroll
    for (int it = 0; it < 2; it++) {
        int f = tid + it * 256;
        int r = f >> 2;
        int c4 = (f & 3) * 4;
        int off = r * GSTR + (c4 & ~7) + ((c4 & 4) ? 1 : 0);
        float* pA = sg;
        float* pB = sg + 2 * GE_TILE;
        pA[off + 0] = f2tff(ra[it].x);
        pA[off + 2] = f2tff(ra[it].y);
        pA[off + 4] = f2tff(ra[it].z);
        pA[off + 6] = f2tff(ra[it].w);
        pB[off + 0] = f2tff(rb[it].x);
        pB[off + 2] = f2tff(rb[it].y);
        pB[off + 4] = f2tff(rb[it].z);
        pB[off + 6] = f2tff(rb[it].w);
    }
    __syncthreads();

    int buf = 0;
    for (int kt = 16; kt <= K; kt += 16) {
        const bool more = (kt < K);
        if (more) {
#pragma unroll
            for (int it = 0; it < 2; it++) {
                int f = tid + it * 256;
                int r = f >> 2;
                int c4 = (f & 3) * 4;
                ra[it] = *(const float4*)(gA + (size_t)r * K + kt + c4);
                rb[it] = *(const float4*)(gB + (size_t)r * K + kt + c4);
            }
        }

        const float* pA = sg + buf * GE_TILE;
        const float* pB = sg + 2 * GE_TILE + buf * GE_TILE;
#pragma unroll
        for (int s = 0; s < 2; s++) {
            uint32_t a[4][4], b[4][2];
#pragma unroll
            for (int i = 0; i < 4; i++) {
                int rw = wm * 64 + i * 16 + g;
                float2 lo = *(const float2*)(pA + rw * GSTR + s * 8 + 2 * t);
                float2 hi = *(const float2*)(pA + (rw + 8) * GSTR + s * 8 + 2 * t);
                a[i][0] = __float_as_uint(lo.x);
                a[i][1] = __float_as_uint(hi.x);
                a[i][2] = __float_as_uint(lo.y);
                a[i][3] = __float_as_uint(hi.y);
            }
#pragma unroll
            for (int j = 0; j < 4; j++) {
                int rn = wn * 32 + j * 8 + g;
                float2 bb = *(const float2*)(pB + rn * GSTR + s * 8 + 2 * t);
                b[j][0] = __float_as_uint(bb.x);
                b[j][1] = __float_as_uint(bb.y);
            }
#pragma unroll
            for (int i = 0; i < 4; i++)
#pragma unroll
                for (int j = 0; j < 4; j++) mma8(d[i][j], a[i], b[j]);
        }

        if (more) {
            float* qA = sg + (buf ^ 1) * GE_TILE;
            float* qB = sg + 2 * GE_TILE + (buf ^ 1) * GE_TILE;
#pragma unroll
            for (int it = 0; it < 2; it++) {
                int f = tid + it * 256;
                int r = f >> 2;
                int c4 = (f & 3) * 4;
                int off = r * GSTR + (c4 & ~7) + ((c4 & 4) ? 1 : 0);
                qA[off + 0] = f2tff(ra[it].x);
                qA[off + 2] = f2tff(ra[it].y);
                qA[off + 4] = f2tff(ra[it].z);
                qA[off + 6] = f2tff(ra[it].w);
                qB[off + 0] = f2tff(rb[it].x);
                qB[off + 2] = f2tff(rb[it].y);
                qB[off + 4] = f2tff(rb[it].z);
                qB[off + 6] = f2tff(rb[it].w);
            }
        }
        buf ^= 1;
        __syncthreads();
    }

#pragma unroll
    for (int i = 0; i < 4; i++) {
        int r0 = m0 + wm * 64 + i * 16 + g;
#pragma unroll
        for (int j = 0; j < 4; j++) {
            int cn = n0 + wn * 32 + j * 8 + t * 2;
            *(float2*)(C + (size_t)r0 * N + cn) = make_float2(d[i][j][0], d[i][j][1]);
            *(float2*)(C + (size_t)(r0 + 8) * N + cn) = make_float2(d[i][j][2], d[i][j][3]);
        }
    }
}

// ---------------------------------------------------------------- flash attention
// CTA = (b, h, 128 query rows), 256 threads / 8 warps; warp owns 16 rows.
// Q (pre-scaled by 0.125) in registers. K smem [key][d perm] stride 72;
// V smem transposed [d][key perm] stride 136. 128-key tiles processed as
// two 64-key softmax halves. P redistributed S->A frag via quad shuffles.
#define KSTR 72
#define VSTR 136
#define KS_FLOATS (128 * KSTR)
#define FL_SMEM ((KS_FLOATS + 64 * VSTR) * 4)

__global__ __launch_bounds__(256, 2) void flash_mma(const float* __restrict__ qp,
                                                    const float* __restrict__ kp,
                                                    const float* __restrict__ vp,
                                                    float* __restrict__ op) {
    extern __shared__ float sm[];
    float* Ks = sm;                 // [key 0..127][d perm] stride 72
    float* Vt = sm + KS_FLOATS;     // [d 0..63][key perm] stride 136

    const int tid = threadIdx.x;
    const int lane = tid & 31;
    const int wid = tid >> 5;
    const int g = lane >> 2;
    const int t = lane & 3;
    const bool odd = (t & 1);
    const int srcA = (lane & ~3) | (t >> 1);
    const int srcB = srcA + 2;
    const int b = blockIdx.z;
    const int h = blockIdx.y;
    const int s0 = blockIdx.x * 128;
    const int r0 = wid * 16 + g;    // query rows r0, r0+8

    // Q fragments, pre-scaled by softmax scale (exact pow2)
    const float* gq = qp + (((size_t)(b * SS + s0)) * HH + h) * DQ;
    uint32_t qa[8][4];
#pragma unroll
    for (int s = 0; s < 8; s++) {
        qa[s][0] = f2tf(0.125f * gq[(size_t)r0 * DM + s * 8 + t]);
        qa[s][1] = f2tf(0.125f * gq[(size_t)(r0 + 8) * DM + s * 8 + t]);
        qa[s][2] = f2tf(0.125f * gq[(size_t)r0 * DM + s * 8 + t + 4]);
        qa[s][3] = f2tf(0.125f * gq[(size_t)(r0 + 8) * DM + s * 8 + t + 4]);
    }

    float m0r = -INFINITY, m1r = -INFINITY, l0 = 0.f, l1 = 0.f;
    float o[8][4];
#pragma unroll
    for (int j = 0; j < 8; j++)
#pragma unroll
        for (int c = 0; c < 4; c++) o[j][c] = 0.f;

    for (int t0 = 0; t0 < SS; t0 += 128) {
        __syncthreads();

        const float* gk = kp + (((size_t)(b * SS + t0)) * HH + h) * DQ;
        const float* gv = vp + (((size_t)(b * SS + t0)) * HH + h) * DQ;
#pragma unroll
        for (int it = 0; it < 8; it++) {
            int f = tid + it * 256;
            int r = f >> 4;            // key
            int c4 = (f & 15) * 4;     // d base (0..60)
            float4 kv = *(const float4*)(gk + (size_t)r * DM + c4);
            // FIX: preserve high column bits: k -> (k&~7) + 2*(k&3) + ((k&4)?1:0)
            int koff = r * KSTR + (c4 & ~7) + ((c4 & 4) ? 1 : 0);
            Ks[koff + 0] = f2tff(kv.x);
            Ks[koff + 2] = f2tff(kv.y);
            Ks[koff + 4] = f2tff(kv.z);
            Ks[koff + 6] = f2tff(kv.w);
            float4 vv = *(const float4*)(gv + (size_t)r * DM + c4);
            int vcol = (r & ~7) + ((r & 3) * 2) + ((r >> 2) & 1);
            Vt[(c4 + 0) * VSTR + vcol] = f2tff(vv.x);
            Vt[(c4 + 1) * VSTR + vcol] = f2tff(vv.y);
            Vt[(c4 + 2) * VSTR + vcol] = f2tff(vv.z);
            Vt[(c4 + 3) * VSTR + vcol] = f2tff(vv.w);
        }
        __syncthreads();

#pragma unroll
        for (int half = 0; half < 2; half++) {
            const int kb = half * 64;   // key base within smem tile

            // S = Q @ K^T : warp tile 16 x 64 (8 n-tiles), K-dim = 64
            float sj[8][4];
#pragma unroll
            for (int j = 0; j < 8; j++)
#pragma unroll
                for (int c = 0; c < 4; c++) sj[j][c] = 0.f;

#pragma unroll
            for (int s = 0; s < 8; s++) {
#pragma unroll
                for (int j = 0; j < 8; j++) {
                    float2 bb = *(const float2*)(Ks + (kb + j * 8 + g) * KSTR +
                                                 s * 8 + 2 * t);
                    uint32_t bfr[2] = {__float_as_uint(bb.x), __float_as_uint(bb.y)};
                    mma8(sj[j], qa[s], bfr);
                }
            }

            // online softmax (rows r0 and r0+8); scale already in Q
            float mx0 = -INFINITY, mx1 = -INFINITY;
#pragma unroll
            for (int j = 0; j < 8; j++) {
                mx0 = fmaxf(mx0, fmaxf(sj[j][0], sj[j][1]));
                mx1 = fmaxf(mx1, fmaxf(sj[j][2], sj[j][3]));
            }
            mx0 = fmaxf(mx0, __shfl_xor_sync(0xffffffffu, mx0, 1));
            mx0 = fmaxf(mx0, __shfl_xor_sync(0xffffffffu, mx0, 2));
            mx1 = fmaxf(mx1, __shfl_xor_sync(0xffffffffu, mx1, 1));
            mx1 = fmaxf(mx1, __shfl_xor_sync(0xffffffffu, mx1, 2));

            float mn0 = fmaxf(m0r, mx0);
            float mn1 = fmaxf(m1r, mx1);
            float al0 = __expf(m0r - mn0);
            float al1 = __expf(m1r - mn1);
            m0r = mn0;
            m1r = mn1;

            float sum0 = 0.f, sum1 = 0.f;
#pragma unroll
            for (int j = 0; j < 8; j++) {
                sj[j][0] = __expf(sj[j][0] - mn0);
                sj[j][1] = __expf(sj[j][1] - mn0);
                sj[j][2] = __expf(sj[j][2] - mn1);
                sj[j][3] = __expf(sj[j][3] - mn1);
                sum0 += sj[j][0] + sj[j][1];
                sum1 += sj[j][2] + sj[j][3];
            }
            sum0 += __shfl_xor_sync(0xffffffffu, sum0, 1);
            sum0 += __shfl_xor_sync(0xffffffffu, sum0, 2);
            sum1 += __shfl_xor_sync(0xffffffffu, sum1, 1);
            sum1 += __shfl_xor_sync(0xffffffffu, sum1, 2);
            l0 = l0 * al0 + sum0;
            l1 = l1 * al1 + sum1;

#pragma unroll
            for (int j = 0; j < 8; j++) {
                o[j][0] *= al0;
                o[j][1] *= al0;
                o[j][2] *= al1;
                o[j][3] *= al1;
            }

            // O += P @ V : redistribute P frag via quad shuffles, B from Vt
#pragma unroll
            for (int s = 0; s < 8; s++) {
                float y0 = __shfl_sync(0xffffffffu, sj[s][0], srcA);
                float y1 = __shfl_sync(0xffffffffu, sj[s][1], srcA);
                float y2 = __shfl_sync(0xffffffffu, sj[s][2], srcA);
                float y3 = __shfl_sync(0xffffffffu, sj[s][3], srcA);
                float z0 = __shfl_sync(0xffffffffu, sj[s][0], srcB);
                float z1 = __shfl_sync(0xffffffffu, sj[s][1], srcB);
                float z2 = __shfl_sync(0xffffffffu, sj[s][2], srcB);
                float z3 = __shfl_sync(0xffffffffu, sj[s][3], srcB);
                uint32_t pa[4];
                pa[0] = f2tf(odd ? y1 : y0);   // (g,    key s*8+t)
                pa[1] = f2tf(odd ? y3 : y2);   // (g+8,  key s*8+t)
                pa[2] = f2tf(odd ? z1 : z0);   // (g,    key s*8+t+4)
                pa[3] = f2tf(odd ? z3 : z2);   // (g+8,  key s*8+t+4)
#pragma unroll
                for (int j = 0; j < 8; j++) {
                    float2 bb = *(const float2*)(Vt + (j * 8 + g) * VSTR + kb +
                                                 s * 8 + 2 * t);
                    uint32_t bfr[2] = {__float_as_uint(bb.x), __float_as_uint(bb.y)};
                    mma8(o[j], pa, bfr);
                }
            }
        }
    }

    // normalize + store heads in [b,h,s,dq]
    float inv0 = 1.f / l0;
    float inv1 = 1.f / l1;
    float* ob = op + (((size_t)(b * HH + h)) * SS + s0) * DQ;
#pragma unroll
    for (int j = 0; j < 8; j++) {
        int cn = j * 8 + t * 2;
        *(float2*)(ob + (size_t)r0 * DQ + cn) =
            make_float2(o[j][0] * inv0, o[j][1] * inv0);
        *(float2*)(ob + (size_t)(r0 + 8) * DQ + cn) =
            make_float2(o[j][2] * inv1, o[j][3] * inv1);
    }
}

// ---------------------------------------------------------------- launch
extern "C" void kernel_launch(void* const* d_in, const int* in_sizes, int n_in,
                              void* d_out, int out_size) {
    const float* xq = (const float*)d_in[0];
    const float* xk = (const float*)d_in[1];
    const float* xv = (const float*)d_in[2];
    const float* Qw = (const float*)d_in[3];
    const float* Kw = (const float*)d_in[4];
    const float* Vw = (const float*)d_in[5];
    const float* Wo = (const float*)d_in[6];
    float* out = (float*)d_out;

    float *pWq, *pWk, *pWv, *pq, *pk, *pv, *ph;
    cudaGetSymbolAddress((void**)&pWq, g_Wq);
    cudaGetSymbolAddress((void**)&pWk, g_Wk);
    cudaGetSymbolAddress((void**)&pWv, g_Wv);
    cudaGetSymbolAddress((void**)&pq, g_q);
    cudaGetSymbolAddress((void**)&pk, g_k);
    cudaGetSymbolAddress((void**)&pv, g_v);
    cudaGetSymbolAddress((void**)&ph, g_h);

    static int attr_done = 0;
    if (!attr_done) {
        cudaFuncSetAttribute(gemm_mma, cudaFuncAttributeMaxDynamicSharedMemorySize,
                             GE_SMEM);
        cudaFuncSetAttribute(flash_mma, cudaFuncAttributeMaxDynamicSharedMemorySize,
                             FL_SMEM);
        attr_done = 1;
    }

    prep_weights<<<(DM * DM + 255) / 256, 256>>>(Qw, Kw, Vw);

    dim3 ggrid(DM / 128, (BB * SS) / 128);
    gemm_mma<<<ggrid, 256, GE_SMEM>>>(xq, pWq, pq, BB * SS, DM, DM);
    gemm_mma<<<ggrid, 256, GE_SMEM>>>(xk, pWk, pk, BB * SS, DM, DM);
    gemm_mma<<<ggrid, 256, GE_SMEM>>>(xv, pWv, pv, BB * SS, DM, DM);

    flash_mma<<<dim3(SS / 128, HH, BB), 256, FL_SMEM>>>(pq, pk, pv, ph);

    gemm_mma<<<ggrid, 256, GE_SMEM>>>(ph, Wo, out, BB * SS, DM, DM);
}

// round 7
// speedup vs baseline: 2.5961x; 1.0495x over previous
#include <cuda_runtime.h>
#include <math.h>
#include <stdint.h>

#define BB 4
#define HH 8
#define SS 2048
#define DM 512
#define DQ 64

// ---------------------------------------------------------------- utils
__device__ __forceinline__ uint32_t f2tf(float x) {
    uint32_t r;
    asm("cvt.rna.tf32.f32 %0, %1;" : "=r"(r) : "f"(x));
    return r;
}
__device__ __forceinline__ float f2tff(float x) {
    return __uint_as_float(f2tf(x));
}
__device__ __forceinline__ float ex2f(float x) {
    float y;
    asm("ex2.approx.f32 %0, %1;" : "=f"(y) : "f"(x));
    return y;
}

// D += A(16x8) @ B(8x8), tf32 inputs, fp32 accum
__device__ __forceinline__ void mma8(float d[4], const uint32_t a[4],
                                     const uint32_t b[2]) {
    asm volatile(
        "mma.sync.aligned.m16n8k8.row.col.f32.tf32.tf32.f32 "
        "{%0,%1,%2,%3}, {%4,%5,%6,%7}, {%8,%9}, {%0,%1,%2,%3};"
        : "+f"(d[0]), "+f"(d[1]), "+f"(d[2]), "+f"(d[3])
        : "r"(a[0]), "r"(a[1]), "r"(a[2]), "r"(a[3]), "r"(b[0]), "r"(b[1]));
}

// pack 8 consecutive k-values (two float4) into interleaved frag order:
// words = (k0,k4,k1,k5) , (k2,k6,k3,k7) so LDS.64 at 2t gives (t, t+4)
__device__ __forceinline__ void pack8(float* dst, float4 v0, float4 v1) {
    *(float4*)dst = make_float4(f2tff(v0.x), f2tff(v1.x), f2tff(v0.y), f2tff(v1.y));
    *(float4*)(dst + 4) =
        make_float4(f2tff(v0.z), f2tff(v1.z), f2tff(v0.w), f2tff(v1.w));
}

// ---------------------------------------------------------------- scratch
__device__ float g_Wq[DM * DM];
__device__ float g_Wk[DM * DM];
__device__ float g_Wv[DM * DM];
__device__ float g_q[BB * SS * DM];   // [b,s,h,dq]
__device__ float g_k[BB * SS * DM];
__device__ float g_v[BB * SS * DM];
__device__ float g_h[BB * SS * DM];   // [b,h,s,dq] == concat view (flat)

__global__ void prep_weights(const float* __restrict__ Qw,
                             const float* __restrict__ Kw,
                             const float* __restrict__ Vw) {
    int i = blockIdx.x * 256 + threadIdx.x;
    if (i >= DM * DM) return;
    int n = i >> 9;
    int d = i & 511;
    int h = n >> 6;
    int q = n & 63;
    int src = (h * DM + d) * DQ + q;
    g_Wq[i] = Qw[src];
    g_Wk[i] = Kw[src];
    g_Wv[i] = Vw[src];
}

// ---------------------------------------------------------------- GEMM
// C[M,N] = A[M,K] @ B[N,K]^T. CTA tile 128x256, BK=16, 256 threads,
// 8 warps (2m x 4n), warp tile 64x64. Double-buffered, STS.128 stores.
#define GSTR 24
#define GAW (128 * GSTR)   // A stage words
#define GBW (256 * GSTR)   // B stage words
#define GE_SMEM ((2 * GAW + 2 * GBW) * 4)

__global__ __launch_bounds__(256) void gemm_mma(const float* __restrict__ A,
                                                const float* __restrict__ B,
                                                float* __restrict__ C,
                                                int M, int N, int K) {
    extern __shared__ float sg[];

    const int tid = threadIdx.x;
    const int lane = tid & 31;
    const int wid = tid >> 5;
    const int g = lane >> 2;
    const int t = lane & 3;
    const int wm = wid & 1;       // m offset wm*64
    const int wn = wid >> 1;      // n offset wn*64
    const int m0 = blockIdx.y * 128;
    const int n0 = blockIdx.x * 256;

    const int aRow = tid >> 1;
    const int k8 = (tid & 1) * 8;

    const float* gA = A + (size_t)(m0 + aRow) * K + k8;
    const float* gB0 = B + (size_t)(n0 + aRow) * K + k8;
    const float* gB1 = gB0 + (size_t)128 * K;

    float d[4][8][4];
#pragma unroll
    for (int i = 0; i < 4; i++)
#pragma unroll
        for (int j = 0; j < 8; j++)
#pragma unroll
            for (int c = 0; c < 4; c++) d[i][j][c] = 0.f;

    float4 fa0, fa1, fb00, fb01, fb10, fb11;
    // prologue: load k-tile 0
    fa0 = *(const float4*)(gA);
    fa1 = *(const float4*)(gA + 4);
    fb00 = *(const float4*)(gB0);
    fb01 = *(const float4*)(gB0 + 4);
    fb10 = *(const float4*)(gB1);
    fb11 = *(const float4*)(gB1 + 4);
    pack8(sg + aRow * GSTR + k8, fa0, fa1);
    pack8(sg + 2 * GAW + aRow * GSTR + k8, fb00, fb01);
    pack8(sg + 2 * GAW + (aRow + 128) * GSTR + k8, fb10, fb11);
    __syncthreads();

    int buf = 0;
    for (int kt = 16; kt <= K; kt += 16) {
        const bool more = (kt < K);
        if (more) {
            fa0 = *(const float4*)(gA + kt);
            fa1 = *(const float4*)(gA + kt + 4);
            fb00 = *(const float4*)(gB0 + kt);
            fb01 = *(const float4*)(gB0 + kt + 4);
            fb10 = *(const float4*)(gB1 + kt);
            fb11 = *(const float4*)(gB1 + kt + 4);
        }

        const float* pA = sg + buf * GAW;
        const float* pB = sg + 2 * GAW + buf * GBW;
#pragma unroll
        for (int s = 0; s < 2; s++) {
            uint32_t a[4][4], b[8][2];
#pragma unroll
            for (int i = 0; i < 4; i++) {
                int rw = wm * 64 + i * 16 + g;
                float2 lo = *(const float2*)(pA + rw * GSTR + s * 8 + 2 * t);
                float2 hi = *(const float2*)(pA + (rw + 8) * GSTR + s * 8 + 2 * t);
                a[i][0] = __float_as_uint(lo.x);
                a[i][1] = __float_as_uint(hi.x);
                a[i][2] = __float_as_uint(lo.y);
                a[i][3] = __float_as_uint(hi.y);
            }
#pragma unroll
            for (int j = 0; j < 8; j++) {
                int rn = wn * 64 + j * 8 + g;
                float2 bb = *(const float2*)(pB + rn * GSTR + s * 8 + 2 * t);
                b[j][0] = __float_as_uint(bb.x);
                b[j][1] = __float_as_uint(bb.y);
            }
#pragma unroll
            for (int i = 0; i < 4; i++)
#pragma unroll
                for (int j = 0; j < 8; j++) mma8(d[i][j], a[i], b[j]);
        }

        if (more) {
            float* qA = sg + (buf ^ 1) * GAW;
            float* qB = sg + 2 * GAW + (buf ^ 1) * GBW;
            pack8(qA + aRow * GSTR + k8, fa0, fa1);
            pack8(qB + aRow * GSTR + k8, fb00, fb01);
            pack8(qB + (aRow + 128) * GSTR + k8, fb10, fb11);
        }
        buf ^= 1;
        __syncthreads();
    }

#pragma unroll
    for (int i = 0; i < 4; i++) {
        int r0 = m0 + wm * 64 + i * 16 + g;
#pragma unroll
        for (int j = 0; j < 8; j++) {
            int cn = n0 + wn * 64 + j * 8 + t * 2;
            *(float2*)(C + (size_t)r0 * N + cn) = make_float2(d[i][j][0], d[i][j][1]);
            *(float2*)(C + (size_t)(r0 + 8) * N + cn) =
                make_float2(d[i][j][2], d[i][j][3]);
        }
    }
}

// ---------------------------------------------------------------- flash attention
// CTA = (b, h, 128 query rows), 128 threads / 4 warps; warp owns 32 rows
// (two m16 tiles) -> each K/V fragment LDS feeds 2 mma. Q in registers
// (pre-scaled by 0.125*log2e; softmax in base 2). 32-key softmax chunks.
#define KSTR 72
#define VSTR 136
#define KS_FLOATS (128 * KSTR)
#define FL_SMEM ((KS_FLOATS + 64 * VSTR) * 4)

__global__ __launch_bounds__(128) void flash_mma(const float* __restrict__ qp,
                                                 const float* __restrict__ kp,
                                                 const float* __restrict__ vp,
                                                 float* __restrict__ op) {
    extern __shared__ float sm[];
    float* Ks = sm;               // [key 0..127][d perm] stride 72
    float* Vt = sm + KS_FLOATS;   // [d 0..63][key perm] stride 136

    const int tid = threadIdx.x;
    const int lane = tid & 31;
    const int wid = tid >> 5;     // 0..3
    const int g = lane >> 2;
    const int t = lane & 3;
    const bool odd = (t & 1);
    const int srcA = (lane & ~3) | (t >> 1);
    const int srcB = srcA + 2;
    const int b = blockIdx.z;
    const int h = blockIdx.y;
    const int s0 = blockIdx.x * 128;
    const int rowbase = wid * 32;

    // Q fragments for 2 row tiles, pre-scaled by 0.125*log2(e)
    const float qscale = 0.125f * 1.4426950408889634f;
    const float* gq = qp + (((size_t)(b * SS + s0)) * HH + h) * DQ;
    uint32_t qa[2][8][4];
#pragma unroll
    for (int i = 0; i < 2; i++) {
        const float* q0 = gq + (size_t)(rowbase + 16 * i + g) * DM;
        const float* q1 = q0 + 8 * DM;
#pragma unroll
        for (int s = 0; s < 8; s++) {
            qa[i][s][0] = f2tf(qscale * q0[s * 8 + t]);
            qa[i][s][1] = f2tf(qscale * q1[s * 8 + t]);
            qa[i][s][2] = f2tf(qscale * q0[s * 8 + t + 4]);
            qa[i][s][3] = f2tf(qscale * q1[s * 8 + t + 4]);
        }
    }

    // m/l for 4 rows: [0]=tile0 row g, [1]=tile0 row g+8, [2]=tile1 g, [3]=tile1 g+8
    float m[4], l[4];
#pragma unroll
    for (int r = 0; r < 4; r++) {
        m[r] = -INFINITY;
        l[r] = 0.f;
    }
    float o[2][8][4];
#pragma unroll
    for (int i = 0; i < 2; i++)
#pragma unroll
        for (int j = 0; j < 8; j++)
#pragma unroll
            for (int c = 0; c < 4; c++) o[i][j][c] = 0.f;

    for (int t0 = 0; t0 < SS; t0 += 128) {
        __syncthreads();

        // load K/V tile: thread handles key row = tid, 8 d-groups
        const float* gkr = kp + (((size_t)(b * SS + t0 + tid)) * HH + h) * DQ;
        const float* gvr = vp + (((size_t)(b * SS + t0 + tid)) * HH + h) * DQ;
        const int vcol = (tid & ~7) + ((tid & 3) * 2) + ((tid >> 2) & 1);
#pragma unroll
        for (int it = 0; it < 8; it++) {
            const int d8 = it * 8;
            float4 k0 = *(const float4*)(gkr + d8);
            float4 k1 = *(const float4*)(gkr + d8 + 4);
            pack8(Ks + tid * KSTR + d8, k0, k1);
            float4 v0 = *(const float4*)(gvr + d8);
            float4 v1 = *(const float4*)(gvr + d8 + 4);
            float* vw = Vt + d8 * VSTR + vcol;
            vw[0 * VSTR] = f2tff(v0.x);
            vw[1 * VSTR] = f2tff(v0.y);
            vw[2 * VSTR] = f2tff(v0.z);
            vw[3 * VSTR] = f2tff(v0.w);
            vw[4 * VSTR] = f2tff(v1.x);
            vw[5 * VSTR] = f2tff(v1.y);
            vw[6 * VSTR] = f2tff(v1.z);
            vw[7 * VSTR] = f2tff(v1.w);
        }
        __syncthreads();

#pragma unroll
        for (int chunk = 0; chunk < 4; chunk++) {
            const int kb = chunk * 32;

            // S = Q @ K^T : 2 row tiles x 4 key groups, K-dim = 64
            float sj[2][4][4];
#pragma unroll
            for (int i = 0; i < 2; i++)
#pragma unroll
                for (int j = 0; j < 4; j++)
#pragma unroll
                    for (int c = 0; c < 4; c++) sj[i][j][c] = 0.f;

#pragma unroll
            for (int s = 0; s < 8; s++) {
#pragma unroll
                for (int j = 0; j < 4; j++) {
                    float2 bb = *(const float2*)(Ks + (kb + j * 8 + g) * KSTR +
                                                 s * 8 + 2 * t);
                    uint32_t bf[2] = {__float_as_uint(bb.x), __float_as_uint(bb.y)};
                    mma8(sj[0][j], qa[0][s], bf);
                    mma8(sj[1][j], qa[1][s], bf);
                }
            }

            // online softmax (base 2) over 32 keys for 4 rows
            float mx[4] = {-INFINITY, -INFINITY, -INFINITY, -INFINITY};
#pragma unroll
            for (int i = 0; i < 2; i++)
#pragma unroll
                for (int j = 0; j < 4; j++) {
                    mx[2 * i + 0] = fmaxf(mx[2 * i + 0], fmaxf(sj[i][j][0], sj[i][j][1]));
                    mx[2 * i + 1] = fmaxf(mx[2 * i + 1], fmaxf(sj[i][j][2], sj[i][j][3]));
                }
            float al[4];
#pragma unroll
            for (int r = 0; r < 4; r++) {
                mx[r] = fmaxf(mx[r], __shfl_xor_sync(0xffffffffu, mx[r], 1));
                mx[r] = fmaxf(mx[r], __shfl_xor_sync(0xffffffffu, mx[r], 2));
                float mn = fmaxf(m[r], mx[r]);
                al[r] = ex2f(m[r] - mn);
                m[r] = mn;
            }
            float sum[4] = {0.f, 0.f, 0.f, 0.f};
#pragma unroll
            for (int i = 0; i < 2; i++)
#pragma unroll
                for (int j = 0; j < 4; j++) {
                    sj[i][j][0] = ex2f(sj[i][j][0] - m[2 * i + 0]);
                    sj[i][j][1] = ex2f(sj[i][j][1] - m[2 * i + 0]);
                    sj[i][j][2] = ex2f(sj[i][j][2] - m[2 * i + 1]);
                    sj[i][j][3] = ex2f(sj[i][j][3] - m[2 * i + 1]);
                    sum[2 * i + 0] += sj[i][j][0] + sj[i][j][1];
                    sum[2 * i + 1] += sj[i][j][2] + sj[i][j][3];
                }
#pragma unroll
            for (int r = 0; r < 4; r++) {
                sum[r] += __shfl_xor_sync(0xffffffffu, sum[r], 1);
                sum[r] += __shfl_xor_sync(0xffffffffu, sum[r], 2);
                l[r] = l[r] * al[r] + sum[r];
            }
#pragma unroll
            for (int i = 0; i < 2; i++)
#pragma unroll
                for (int j = 0; j < 8; j++) {
                    o[i][j][0] *= al[2 * i + 0];
                    o[i][j][1] *= al[2 * i + 0];
                    o[i][j][2] *= al[2 * i + 1];
                    o[i][j][3] *= al[2 * i + 1];
                }

            // O += P @ V : 4 key-groups, V frag shared by both row tiles
#pragma unroll
            for (int s = 0; s < 4; s++) {
                uint32_t pa[2][4];
#pragma unroll
                for (int i = 0; i < 2; i++) {
                    float y0 = __shfl_sync(0xffffffffu, sj[i][s][0], srcA);
                    float y1 = __shfl_sync(0xffffffffu, sj[i][s][1], srcA);
                    float y2 = __shfl_sync(0xffffffffu, sj[i][s][2], srcA);
                    float y3 = __shfl_sync(0xffffffffu, sj[i][s][3], srcA);
                    float z0 = __shfl_sync(0xffffffffu, sj[i][s][0], srcB);
                    float z1 = __shfl_sync(0xffffffffu, sj[i][s][1], srcB);
                    float z2 = __shfl_sync(0xffffffffu, sj[i][s][2], srcB);
                    float z3 = __shfl_sync(0xffffffffu, sj[i][s][3], srcB);
                    pa[i][0] = f2tf(odd ? y1 : y0);
                    pa[i][1] = f2tf(odd ? y3 : y2);
                    pa[i][2] = f2tf(odd ? z1 : z0);
                    pa[i][3] = f2tf(odd ? z3 : z2);
                }
#pragma unroll
                for (int j = 0; j < 8; j++) {
                    float2 bb = *(const float2*)(Vt + (j * 8 + g) * VSTR + kb +
                                                 s * 8 + 2 * t);
                    uint32_t bf[2] = {__float_as_uint(bb.x), __float_as_uint(bb.y)};
                    mma8(o[0][j], pa[0], bf);
                    mma8(o[1][j], pa[1], bf);
                }
            }
        }
    }

    // normalize + store heads in [b,h,s,dq]
    float* ob = op + (((size_t)(b * HH + h)) * SS + s0) * DQ;
#pragma unroll
    for (int i = 0; i < 2; i++) {
        int rA = rowbase + 16 * i + g;
        float inv0 = 1.f / l[2 * i + 0];
        float inv1 = 1.f / l[2 * i + 1];
#pragma unroll
        for (int j = 0; j < 8; j++) {
            int cn = j * 8 + t * 2;
            *(float2*)(ob + (size_t)rA * DQ + cn) =
                make_float2(o[i][j][0] * inv0, o[i][j][1] * inv0);
            *(float2*)(ob + (size_t)(rA + 8) * DQ + cn) =
                make_float2(o[i][j][2] * inv1, o[i][j][3] * inv1);
        }
    }
}

// ---------------------------------------------------------------- launch
extern "C" void kernel_launch(void* const* d_in, const int* in_sizes, int n_in,
                              void* d_out, int out_size) {
    const float* xq = (const float*)d_in[0];
    const float* xk = (const float*)d_in[1];
    const float* xv = (const float*)d_in[2];
    const float* Qw = (const float*)d_in[3];
    const float* Kw = (const float*)d_in[4];
    const float* Vw = (const float*)d_in[5];
    const float* Wo = (const float*)d_in[6];
    float* out = (float*)d_out;

    float *pWq, *pWk, *pWv, *pq, *pk, *pv, *ph;
    cudaGetSymbolAddress((void**)&pWq, g_Wq);
    cudaGetSymbolAddress((void**)&pWk, g_Wk);
    cudaGetSymbolAddress((void**)&pWv, g_Wv);
    cudaGetSymbolAddress((void**)&pq, g_q);
    cudaGetSymbolAddress((void**)&pk, g_k);
    cudaGetSymbolAddress((void**)&pv, g_v);
    cudaGetSymbolAddress((void**)&ph, g_h);

    static int attr_done = 0;
    if (!attr_done) {
        cudaFuncSetAttribute(gemm_mma, cudaFuncAttributeMaxDynamicSharedMemorySize,
                             GE_SMEM);
        cudaFuncSetAttribute(flash_mma, cudaFuncAttributeMaxDynamicSharedMemorySize,
                             FL_SMEM);
        attr_done = 1;
    }

    prep_weights<<<(DM * DM + 255) / 256, 256>>>(Qw, Kw, Vw);

    dim3 ggrid(DM / 256, (BB * SS) / 128);   // (2, 64)
    gemm_mma<<<ggrid, 256, GE_SMEM>>>(xq, pWq, pq, BB * SS, DM, DM);
    gemm_mma<<<ggrid, 256, GE_SMEM>>>(xk, pWk, pk, BB * SS, DM, DM);
    gemm_mma<<<ggrid, 256, GE_SMEM>>>(xv, pWv, pv, BB * SS, DM, DM);

    flash_mma<<<dim3(SS / 128, HH, BB), 128, FL_SMEM>>>(pq, pk, pv, ph);

    gemm_mma<<<ggrid, 256, GE_SMEM>>>(ph, Wo, out, BB * SS, DM, DM);
}

// round 8
// speedup vs baseline: 4.7885x; 1.8445x over previous
#include <cuda_runtime.h>
#include <cuda_fp16.h>
#include <math.h>
#include <stdint.h>

#define BB 4
#define HH 8
#define SS 2048
#define DM 512
#define DQ 64

// ---------------------------------------------------------------- utils
__device__ __forceinline__ float ex2f(float x) {
    float y;
    asm("ex2.approx.f32 %0, %1;" : "=f"(y) : "f"(x));
    return y;
}
__device__ __forceinline__ uint32_t fh2(float a, float b) {
    __half2 h = __floats2half2_rn(a, b);
    return *reinterpret_cast<uint32_t*>(&h);
}
// D += A(16x16) @ B(16x8), fp16 inputs, fp32 accum
__device__ __forceinline__ void mma16(float d[4], const uint32_t a[4],
                                      const uint32_t b[2]) {
    asm volatile(
        "mma.sync.aligned.m16n8k16.row.col.f32.f16.f16.f32 "
        "{%0,%1,%2,%3}, {%4,%5,%6,%7}, {%8,%9}, {%0,%1,%2,%3};"
        : "+f"(d[0]), "+f"(d[1]), "+f"(d[2]), "+f"(d[3])
        : "r"(a[0]), "r"(a[1]), "r"(a[2]), "r"(a[3]), "r"(b[0]), "r"(b[1]));
}

// permuted pack of 16 logical halves into fragment-friendly order:
// phys = [0,1,8,9,2,3,10,11 | 4,5,12,13,6,7,14,15]
__device__ __forceinline__ void pack16(__half* dst, const float* v) {
    __half2* d2 = reinterpret_cast<__half2*>(dst);
    d2[0] = __floats2half2_rn(v[0], v[1]);
    d2[1] = __floats2half2_rn(v[8], v[9]);
    d2[2] = __floats2half2_rn(v[2], v[3]);
    d2[3] = __floats2half2_rn(v[10], v[11]);
    d2[4] = __floats2half2_rn(v[4], v[5]);
    d2[5] = __floats2half2_rn(v[12], v[13]);
    d2[6] = __floats2half2_rn(v[6], v[7]);
    d2[7] = __floats2half2_rn(v[14], v[15]);
}

// ---------------------------------------------------------------- scratch (half)
__device__ __half g_xqh[BB * SS * DM];
__device__ __half g_xkh[BB * SS * DM];
__device__ __half g_xvh[BB * SS * DM];
__device__ __half g_Wqh[DM * DM];
__device__ __half g_Wkh[DM * DM];
__device__ __half g_Wvh[DM * DM];
__device__ __half g_Woh[DM * DM];
__device__ __half g_qh[BB * SS * DM];   // [b,s,h,dq] permuted-dq
__device__ __half g_kh[BB * SS * DM];
__device__ __half g_vh[BB * SS * DM];
__device__ __half g_hh[BB * SS * DM];   // [b,h,s,dq] == concat view, permuted

// ---------------------------------------------------------------- conversions
__global__ void convert_x(const float* __restrict__ x0,
                          const float* __restrict__ x1,
                          const float* __restrict__ x2) {
    int gidx = blockIdx.x * 256 + threadIdx.x;   // group of 16
    const float* src = (blockIdx.y == 0 ? x0 : (blockIdx.y == 1 ? x1 : x2));
    __half* dst = (blockIdx.y == 0 ? g_xqh : (blockIdx.y == 1 ? g_xkh : g_xvh));
    src += (size_t)gidx * 16;
    dst += (size_t)gidx * 16;
    float v[16];
#pragma unroll
    for (int i = 0; i < 4; i++) {
        float4 f = *(const float4*)(src + i * 4);
        v[i * 4 + 0] = f.x;
        v[i * 4 + 1] = f.y;
        v[i * 4 + 2] = f.z;
        v[i * 4 + 3] = f.w;
    }
    pack16(dst, v);
}

// weights -> [n][k] half, k permuted; Wq scaled by 0.125*log2(e)
__global__ void prep_w(const float* __restrict__ Qw, const float* __restrict__ Kw,
                       const float* __restrict__ Vw, const float* __restrict__ Wo) {
    int idx = blockIdx.x * 256 + threadIdx.x;    // 512*32
    int n = idx >> 5;
    int grp = idx & 31;
    int hh = n >> 6, q = n & 63;
    const float SC = 0.125f * 1.4426950408889634f;
    float wq[16], wk[16], wv[16], wo[16];
#pragma unroll
    for (int l = 0; l < 16; l++) {
        int d = grp * 16 + l;
        int src = (hh * DM + d) * DQ + q;
        wq[l] = Qw[src] * SC;
        wk[l] = Kw[src];
        wv[l] = Vw[src];
        wo[l] = Wo[n * DM + d];
    }
    pack16(g_Wqh + n * DM + grp * 16, wq);
    pack16(g_Wkh + n * DM + grp * 16, wk);
    pack16(g_Wvh + n * DM + grp * 16, wv);
    pack16(g_Woh + n * DM + grp * 16, wo);
}

// ---------------------------------------------------------------- GEMM (fp16)
// C[M,N] = A[M,K] @ B[N,K]^T, half permuted inputs. CTA 128x128, BK=32,
// 256 threads, 8 warps (2m x 4n), warp tile 64x32. Stride 48 halves
// (12 units == 12 mod 16 -> conflict-free frags AND stores). Double buffer.
#define GSH 48
#define GTW (128 * GSH)                 // halves per matrix per stage
#define GE_SMEM (4 * GTW * 2)           // bytes

template <bool HOUT>
__global__ __launch_bounds__(256, 2) void gemm_h(const __half* __restrict__ A,
                                                 const __half* __restrict__ B,
                                                 void* __restrict__ Cv,
                                                 int M, int N, int K) {
    extern __shared__ __half sg[];

    const int tid = threadIdx.x;
    const int lane = tid & 31;
    const int wid = tid >> 5;
    const int g = lane >> 2;
    const int t = lane & 3;
    const int wm = wid & 1;
    const int wn = wid >> 1;
    const int m0 = blockIdx.y * 128;
    const int n0 = blockIdx.x * 128;

    const int aRow = tid >> 1;
    const int c0 = tid & 1;              // chunks c0, c0+2

    const __half* gA = A + (size_t)(m0 + aRow) * K;
    const __half* gB = B + (size_t)(n0 + aRow) * K;

    float d[4][4][4];
#pragma unroll
    for (int i = 0; i < 4; i++)
#pragma unroll
        for (int j = 0; j < 4; j++)
#pragma unroll
            for (int c = 0; c < 4; c++) d[i][j][c] = 0.f;

    uint4 la[2], lb[2];
    la[0] = *(const uint4*)(gA + c0 * 8);
    la[1] = *(const uint4*)(gA + (c0 + 2) * 8);
    lb[0] = *(const uint4*)(gB + c0 * 8);
    lb[1] = *(const uint4*)(gB + (c0 + 2) * 8);
    {
        uint4* sA = (uint4*)(sg + aRow * GSH);
        uint4* sB = (uint4*)(sg + 2 * GTW + aRow * GSH);
        sA[c0] = la[0];
        sA[c0 + 2] = la[1];
        sB[c0] = lb[0];
        sB[c0 + 2] = lb[1];
    }
    __syncthreads();

    int buf = 0;
    for (int kt = 32; kt <= K; kt += 32) {
        const bool more = (kt < K);
        if (more) {
            la[0] = *(const uint4*)(gA + kt + c0 * 8);
            la[1] = *(const uint4*)(gA + kt + (c0 + 2) * 8);
            lb[0] = *(const uint4*)(gB + kt + c0 * 8);
            lb[1] = *(const uint4*)(gB + kt + (c0 + 2) * 8);
        }

        const __half* pA = sg + buf * GTW;
        const __half* pB = sg + 2 * GTW + buf * GTW;
#pragma unroll
        for (int s = 0; s < 2; s++) {
            uint32_t a[4][4], b[4][2];
#pragma unroll
            for (int i = 0; i < 4; i++) {
                int rw = wm * 64 + i * 16 + g;
                uint2 lo = *(const uint2*)(pA + rw * GSH + s * 16 + 4 * t);
                uint2 hi = *(const uint2*)(pA + (rw + 8) * GSH + s * 16 + 4 * t);
                a[i][0] = lo.x;
                a[i][1] = hi.x;
                a[i][2] = lo.y;
                a[i][3] = hi.y;
            }
#pragma unroll
            for (int j = 0; j < 4; j++) {
                int rn = wn * 32 + j * 8 + g;
                uint2 bb = *(const uint2*)(pB + rn * GSH + s * 16 + 4 * t);
                b[j][0] = bb.x;
                b[j][1] = bb.y;
            }
#pragma unroll
            for (int i = 0; i < 4; i++)
#pragma unroll
                for (int j = 0; j < 4; j++) mma16(d[i][j], a[i], b[j]);
        }

        if (more) {
            uint4* qA = (uint4*)(sg + (buf ^ 1) * GTW + aRow * GSH);
            uint4* qB = (uint4*)(sg + 2 * GTW + (buf ^ 1) * GTW + aRow * GSH);
            qA[c0] = la[0];
            qA[c0 + 2] = la[1];
            qB[c0] = lb[0];
            qB[c0 + 2] = lb[1];
        }
        buf ^= 1;
        __syncthreads();
    }

    if (HOUT) {
        __half* C = (__half*)Cv;
#pragma unroll
        for (int i = 0; i < 4; i++) {
            int r0 = m0 + wm * 64 + i * 16 + g;
#pragma unroll
            for (int j = 0; j < 4; j++) {
                // permuted half store: n-group = wn*2 + (j>>1)
                int colh = n0 + (wn * 2 + (j >> 1)) * 16 + 4 * t + 2 * (j & 1);
                *(uint32_t*)(C + (size_t)r0 * N + colh) = fh2(d[i][j][0], d[i][j][1]);
                *(uint32_t*)(C + (size_t)(r0 + 8) * N + colh) =
                    fh2(d[i][j][2], d[i][j][3]);
            }
        }
    } else {
        float* C = (float*)Cv;
#pragma unroll
        for (int i = 0; i < 4; i++) {
            int r0 = m0 + wm * 64 + i * 16 + g;
#pragma unroll
            for (int j = 0; j < 4; j++) {
                int cn = n0 + wn * 32 + j * 8 + t * 2;
                *(float2*)(C + (size_t)r0 * N + cn) =
                    make_float2(d[i][j][0], d[i][j][1]);
                *(float2*)(C + (size_t)(r0 + 8) * N + cn) =
                    make_float2(d[i][j][2], d[i][j][3]);
            }
        }
    }
}

// ---------------------------------------------------------------- flash (fp16)
// CTA = (b, h, 128 query rows), 128 threads / 4 warps, warp owns 32 rows.
// Q frags from gmem (pre-scaled via Wq). K smem [key][d] stride 80 halves;
// V smem transposed [d][key-perm] stride 144. S-frag == P-frag (no shuffles).
#define KSH 80
#define VSH 144
#define KS_HALVES (128 * KSH)
#define FL_SMEM ((128 * KSH + 64 * VSH) * 2)

__global__ __launch_bounds__(128, 3) void flash_h(const __half* __restrict__ qp,
                                                  const __half* __restrict__ kp,
                                                  const __half* __restrict__ vp,
                                                  __half* __restrict__ op) {
    extern __shared__ __half sm[];
    __half* Ks = sm;
    __half* Vt = sm + KS_HALVES;

    const int tid = threadIdx.x;
    const int lane = tid & 31;
    const int wid = tid >> 5;
    const int g = lane >> 2;
    const int t = lane & 3;
    const int b = blockIdx.z;
    const int h = blockIdx.y;
    const int s0 = blockIdx.x * 128;
    const int rowbase = wid * 32;

    // Q fragments (scale folded into Wq): 2 rowtiles x 4 k16 groups
    const __half* gq = qp + ((size_t)(b * SS + s0) * HH + h) * DQ;
    uint32_t qa[2][4][4];
#pragma unroll
    for (int i = 0; i < 2; i++) {
        const __half* q0 = gq + (size_t)(rowbase + 16 * i + g) * DM;
        const __half* q1 = q0 + 8 * DM;
#pragma unroll
        for (int s = 0; s < 4; s++) {
            uint2 u0 = *(const uint2*)(q0 + s * 16 + 4 * t);
            uint2 u1 = *(const uint2*)(q1 + s * 16 + 4 * t);
            qa[i][s][0] = u0.x;
            qa[i][s][1] = u1.x;
            qa[i][s][2] = u0.y;
            qa[i][s][3] = u1.y;
        }
    }

    float m[4], l[4];
#pragma unroll
    for (int r = 0; r < 4; r++) {
        m[r] = -INFINITY;
        l[r] = 0.f;
    }
    float o[2][8][4];
#pragma unroll
    for (int i = 0; i < 2; i++)
#pragma unroll
        for (int j = 0; j < 8; j++)
#pragma unroll
            for (int c = 0; c < 4; c++) o[i][j][c] = 0.f;

    for (int t0 = 0; t0 < SS; t0 += 128) {
        __syncthreads();

        if (tid < 64) {
            // V transpose: keys 2*tid, 2*tid+1 -> Vt[d][key-perm]
            const __half* v0 = vp + ((size_t)(b * SS + t0 + 2 * tid) * HH + h) * DQ;
            const __half* v1 = v0 + DM;
            int grp = tid >> 3, p = tid & 7;
            int colh = grp * 16 + ((p & 3) * 2 + (p >> 2)) * 2;
#pragma unroll
            for (int c = 0; c < 8; c++) {
                uint4 ua = *(const uint4*)(v0 + c * 8);
                uint4 ub = *(const uint4*)(v1 + c * 8);
                const __half* ah = (const __half*)&ua;
                const __half* bh = (const __half*)&ub;
#pragma unroll
                for (int mm = 0; mm < 8; mm++) {
                    *(__half2*)(Vt + (size_t)(c * 8 + mm) * VSH + colh) =
                        __halves2half2(ah[mm], bh[mm]);
                }
            }
        } else {
            // K copy: rows 2j, 2j+1 (chunk order rotated: conflict-free)
            int j = tid - 64;
            const __half* k0 = kp + ((size_t)(b * SS + t0 + 2 * j) * HH + h) * DQ;
#pragma unroll
            for (int r2 = 0; r2 < 2; r2++) {
                const uint4* src = (const uint4*)(k0 + r2 * DM);
                uint4* dst = (uint4*)(Ks + (size_t)(2 * j + r2) * KSH);
#pragma unroll
                for (int mm = 0; mm < 8; mm++) {
                    int c = (mm + j) & 7;
                    dst[c] = src[c];
                }
            }
        }
        __syncthreads();

#pragma unroll
        for (int chunk = 0; chunk < 4; chunk++) {
            const int kb = chunk * 32;

            float sj[2][4][4];
#pragma unroll
            for (int i = 0; i < 2; i++)
#pragma unroll
                for (int j = 0; j < 4; j++)
#pragma unroll
                    for (int c = 0; c < 4; c++) sj[i][j][c] = 0.f;

#pragma unroll
            for (int s = 0; s < 4; s++) {
#pragma unroll
                for (int j = 0; j < 4; j++) {
                    uint2 bb = *(const uint2*)(Ks + (size_t)(kb + j * 8 + g) * KSH +
                                               s * 16 + 4 * t);
                    uint32_t bf[2] = {bb.x, bb.y};
                    mma16(sj[0][j], qa[0][s], bf);
                    mma16(sj[1][j], qa[1][s], bf);
                }
            }

            // online softmax (base 2; scale folded into Q)
            float mx[4] = {-INFINITY, -INFINITY, -INFINITY, -INFINITY};
#pragma unroll
            for (int i = 0; i < 2; i++)
#pragma unroll
                for (int j = 0; j < 4; j++) {
                    mx[2 * i + 0] = fmaxf(mx[2 * i + 0], fmaxf(sj[i][j][0], sj[i][j][1]));
                    mx[2 * i + 1] = fmaxf(mx[2 * i + 1], fmaxf(sj[i][j][2], sj[i][j][3]));
                }
            float al[4];
#pragma unroll
            for (int r = 0; r < 4; r++) {
                mx[r] = fmaxf(mx[r], __shfl_xor_sync(0xffffffffu, mx[r], 1));
                mx[r] = fmaxf(mx[r], __shfl_xor_sync(0xffffffffu, mx[r], 2));
                float mn = fmaxf(m[r], mx[r]);
                al[r] = ex2f(m[r] - mn);
                m[r] = mn;
            }
            float sum[4] = {0.f, 0.f, 0.f, 0.f};
#pragma unroll
            for (int i = 0; i < 2; i++)
#pragma unroll
                for (int j = 0; j < 4; j++) {
                    sj[i][j][0] = ex2f(sj[i][j][0] - m[2 * i + 0]);
                    sj[i][j][1] = ex2f(sj[i][j][1] - m[2 * i + 0]);
                    sj[i][j][2] = ex2f(sj[i][j][2] - m[2 * i + 1]);
                    sj[i][j][3] = ex2f(sj[i][j][3] - m[2 * i + 1]);
                    sum[2 * i + 0] += sj[i][j][0] + sj[i][j][1];
                    sum[2 * i + 1] += sj[i][j][2] + sj[i][j][3];
                }
#pragma unroll
            for (int r = 0; r < 4; r++) {
                sum[r] += __shfl_xor_sync(0xffffffffu, sum[r], 1);
                sum[r] += __shfl_xor_sync(0xffffffffu, sum[r], 2);
                l[r] = l[r] * al[r] + sum[r];
            }
#pragma unroll
            for (int i = 0; i < 2; i++)
#pragma unroll
                for (int j = 0; j < 8; j++) {
                    o[i][j][0] *= al[2 * i + 0];
                    o[i][j][1] *= al[2 * i + 0];
                    o[i][j][2] *= al[2 * i + 1];
                    o[i][j][3] *= al[2 * i + 1];
                }

            // O += P @ V  (S frag repacks directly into A frag)
#pragma unroll
            for (int G = 0; G < 2; G++) {
                uint32_t pa[2][4];
#pragma unroll
                for (int i = 0; i < 2; i++) {
                    pa[i][0] = fh2(sj[i][2 * G][0], sj[i][2 * G][1]);
                    pa[i][1] = fh2(sj[i][2 * G][2], sj[i][2 * G][3]);
                    pa[i][2] = fh2(sj[i][2 * G + 1][0], sj[i][2 * G + 1][1]);
                    pa[i][3] = fh2(sj[i][2 * G + 1][2], sj[i][2 * G + 1][3]);
                }
                int kg = chunk * 2 + G;
#pragma unroll
                for (int j = 0; j < 8; j++) {
                    uint2 bb = *(const uint2*)(Vt + (size_t)(j * 8 + g) * VSH +
                                               kg * 16 + 4 * t);
                    uint32_t bf[2] = {bb.x, bb.y};
                    mma16(o[0][j], pa[0], bf);
                    mma16(o[1][j], pa[1], bf);
                }
            }
        }
    }

    // normalize + store heads (half, phys layout matches final-GEMM perm)
    __half* ob = op + ((size_t)(b * HH + h) * SS + s0) * DQ;
#pragma unroll
    for (int i = 0; i < 2; i++) {
        int rA = rowbase + 16 * i + g;
        float inv0 = 1.f / l[2 * i + 0];
        float inv1 = 1.f / l[2 * i + 1];
#pragma unroll
        for (int j = 0; j < 8; j++) {
            int cn = j * 8 + t * 2;
            *(uint32_t*)(ob + (size_t)rA * DQ + cn) =
                fh2(o[i][j][0] * inv0, o[i][j][1] * inv0);
            *(uint32_t*)(ob + (size_t)(rA + 8) * DQ + cn) =
                fh2(o[i][j][2] * inv1, o[i][j][3] * inv1);
        }
    }
}

// ---------------------------------------------------------------- launch
extern "C" void kernel_launch(void* const* d_in, const int* in_sizes, int n_in,
                              void* d_out, int out_size) {
    const float* xq = (const float*)d_in[0];
    const float* xk = (const float*)d_in[1];
    const float* xv = (const float*)d_in[2];
    const float* Qw = (const float*)d_in[3];
    const float* Kw = (const float*)d_in[4];
    const float* Vw = (const float*)d_in[5];
    const float* Wo = (const float*)d_in[6];
    float* out = (float*)d_out;

    __half *pxq, *pxk, *pxv, *pWq, *pWk, *pWv, *pWo, *pq, *pk, *pv, *ph;
    cudaGetSymbolAddress((void**)&pxq, g_xqh);
    cudaGetSymbolAddress((void**)&pxk, g_xkh);
    cudaGetSymbolAddress((void**)&pxv, g_xvh);
    cudaGetSymbolAddress((void**)&pWq, g_Wqh);
    cudaGetSymbolAddress((void**)&pWk, g_Wkh);
    cudaGetSymbolAddress((void**)&pWv, g_Wvh);
    cudaGetSymbolAddress((void**)&pWo, g_Woh);
    cudaGetSymbolAddress((void**)&pq, g_qh);
    cudaGetSymbolAddress((void**)&pk, g_kh);
    cudaGetSymbolAddress((void**)&pv, g_vh);
    cudaGetSymbolAddress((void**)&ph, g_hh);

    static int attr_done = 0;
    if (!attr_done) {
        cudaFuncSetAttribute(gemm_h<true>,
                             cudaFuncAttributeMaxDynamicSharedMemorySize, GE_SMEM);
        cudaFuncSetAttribute(gemm_h<false>,
                             cudaFuncAttributeMaxDynamicSharedMemorySize, GE_SMEM);
        cudaFuncSetAttribute(flash_h,
                             cudaFuncAttributeMaxDynamicSharedMemorySize, FL_SMEM);
        attr_done = 1;
    }

    convert_x<<<dim3(1024, 3), 256>>>(xq, xk, xv);
    prep_w<<<64, 256>>>(Qw, Kw, Vw, Wo);

    dim3 ggrid(DM / 128, (BB * SS) / 128);   // (4, 64)
    gemm_h<true><<<ggrid, 256, GE_SMEM>>>(pxq, pWq, pq, BB * SS, DM, DM);
    gemm_h<true><<<ggrid, 256, GE_SMEM>>>(pxk, pWk, pk, BB * SS, DM, DM);
    gemm_h<true><<<ggrid, 256, GE_SMEM>>>(pxv, pWv, pv, BB * SS, DM, DM);

    flash_h<<<dim3(SS / 128, HH, BB), 128, FL_SMEM>>>(pq, pk, pv, ph);

    gemm_h<false><<<ggrid, 256, GE_SMEM>>>(ph, pWo, out, BB * SS, DM, DM);
}

// round 9
// speedup vs baseline: 5.3913x; 1.1259x over previous
#include <cuda_runtime.h>
#include <cuda_fp16.h>
#include <math.h>
#include <stdint.h>

#define BB 4
#define HH 8
#define SS 2048
#define DM 512
#define DQ 64

// ---------------------------------------------------------------- utils
__device__ __forceinline__ float ex2f(float x) {
    float y;
    asm("ex2.approx.f32 %0, %1;" : "=f"(y) : "f"(x));
    return y;
}
__device__ __forceinline__ uint32_t fh2(float a, float b) {
    __half2 h = __floats2half2_rn(a, b);
    return *reinterpret_cast<uint32_t*>(&h);
}
// D += A(16x16) @ B(16x8), fp16 inputs, fp32 accum
__device__ __forceinline__ void mma16(float d[4], const uint32_t a[4],
                                      const uint32_t b[2]) {
    asm volatile(
        "mma.sync.aligned.m16n8k16.row.col.f32.f16.f16.f32 "
        "{%0,%1,%2,%3}, {%4,%5,%6,%7}, {%8,%9}, {%0,%1,%2,%3};"
        : "+f"(d[0]), "+f"(d[1]), "+f"(d[2]), "+f"(d[3])
        : "r"(a[0]), "r"(a[1]), "r"(a[2]), "r"(a[3]), "r"(b[0]), "r"(b[1]));
}

// permuted pack of 16 logical halves into fragment order:
// phys = [0,1,8,9,2,3,10,11 | 4,5,12,13,6,7,14,15]
__device__ __forceinline__ void pack16(__half* dst, const float* v) {
    __half2* d2 = reinterpret_cast<__half2*>(dst);
    d2[0] = __floats2half2_rn(v[0], v[1]);
    d2[1] = __floats2half2_rn(v[8], v[9]);
    d2[2] = __floats2half2_rn(v[2], v[3]);
    d2[3] = __floats2half2_rn(v[10], v[11]);
    d2[4] = __floats2half2_rn(v[4], v[5]);
    d2[5] = __floats2half2_rn(v[12], v[13]);
    d2[6] = __floats2half2_rn(v[6], v[7]);
    d2[7] = __floats2half2_rn(v[14], v[15]);
}

// ---------------------------------------------------------------- scratch (half)
__device__ __half g_Wqh[DM * DM];
__device__ __half g_Wkh[DM * DM];
__device__ __half g_Wvh[DM * DM];
__device__ __half g_Woh[DM * DM];
__device__ __half g_qh[BB * SS * DM];   // [b,s,h,dq] permuted-dq
__device__ __half g_kh[BB * SS * DM];
__device__ __half g_vh[BB * SS * DM];
__device__ __half g_hh[BB * SS * DM];   // [b,h,s,dq] == concat view, permuted

// weights -> [n][k] half, k permuted; Wq scaled by 0.125*log2(e)
__global__ void prep_w(const float* __restrict__ Qw, const float* __restrict__ Kw,
                       const float* __restrict__ Vw, const float* __restrict__ Wo) {
    int idx = blockIdx.x * 256 + threadIdx.x;    // 512*32
    int n = idx >> 5;
    int grp = idx & 31;
    int hh = n >> 6, q = n & 63;
    const float SC = 0.125f * 1.4426950408889634f;
    float wq[16], wk[16], wv[16], wo[16];
#pragma unroll
    for (int l = 0; l < 16; l++) {
        int d = grp * 16 + l;
        int src = (hh * DM + d) * DQ + q;
        wq[l] = Qw[src] * SC;
        wk[l] = Kw[src];
        wv[l] = Vw[src];
        wo[l] = Wo[n * DM + d];
    }
    pack16(g_Wqh + n * DM + grp * 16, wq);
    pack16(g_Wkh + n * DM + grp * 16, wk);
    pack16(g_Wvh + n * DM + grp * 16, wv);
    pack16(g_Woh + n * DM + grp * 16, wo);
}

// ---------------------------------------------------------------- GEMM common
// CTA 128x128, BK=32, 256 threads, 8 warps (2m x 4n), warp tile 64x32.
// Stride 48 halves; double-buffered smem.
#define GSH 48
#define GTW (128 * GSH)
#define GE_SMEM (4 * GTW * 2)

// fused projection GEMM: A fp32 (converted+permuted on the fly), B = weights
// (device globals), C half permuted. blockIdx.z selects q/k/v.
__global__ __launch_bounds__(256, 2) void gemm_qkv(const float* __restrict__ xq,
                                                   const float* __restrict__ xk,
                                                   const float* __restrict__ xv) {
    extern __shared__ __half sg[];
    const int z = blockIdx.z;
    const float* A = (z == 0) ? xq : (z == 1) ? xk : xv;
    const __half* B = (z == 0) ? g_Wqh : (z == 1) ? g_Wkh : g_Wvh;
    __half* C = (z == 0) ? g_qh : (z == 1) ? g_kh : g_vh;
    const int M = BB * SS, N = DM, K = DM;

    const int tid = threadIdx.x;
    const int lane = tid & 31;
    const int wid = tid >> 5;
    const int g = lane >> 2;
    const int t = lane & 3;
    const int wm = wid & 1;
    const int wn = wid >> 1;
    const int m0 = blockIdx.y * 128;
    const int n0 = blockIdx.x * 128;

    const int aRow = tid >> 1;
    const int c0 = tid & 1;

    const float* gAf = A + (size_t)(m0 + aRow) * K;
    const __half* gB = B + (size_t)(n0 + aRow) * K;

    float d[4][4][4];
#pragma unroll
    for (int i = 0; i < 4; i++)
#pragma unroll
        for (int j = 0; j < 4; j++)
#pragma unroll
            for (int c = 0; c < 4; c++) d[i][j][c] = 0.f;

    uint4 la[2], lb[2];
#pragma unroll
    for (int gi = 0; gi < 2; gi++) {
        float4 p0 = *(const float4*)(gAf + gi * 16 + c0 * 4);
        float4 p1 = *(const float4*)(gAf + gi * 16 + c0 * 4 + 8);
        la[gi] = make_uint4(fh2(p0.x, p0.y), fh2(p1.x, p1.y), fh2(p0.z, p0.w),
                            fh2(p1.z, p1.w));
    }
    lb[0] = *(const uint4*)(gB + c0 * 8);
    lb[1] = *(const uint4*)(gB + (c0 + 2) * 8);
    {
        uint4* sA = (uint4*)(sg + aRow * GSH);
        uint4* sB = (uint4*)(sg + 2 * GTW + aRow * GSH);
        sA[c0] = la[0];
        sA[c0 + 2] = la[1];
        sB[c0] = lb[0];
        sB[c0 + 2] = lb[1];
    }
    __syncthreads();

    int buf = 0;
    for (int kt = 32; kt <= K; kt += 32) {
        const bool more = (kt < K);
        if (more) {
#pragma unroll
            for (int gi = 0; gi < 2; gi++) {
                float4 p0 = *(const float4*)(gAf + kt + gi * 16 + c0 * 4);
                float4 p1 = *(const float4*)(gAf + kt + gi * 16 + c0 * 4 + 8);
                la[gi] = make_uint4(fh2(p0.x, p0.y), fh2(p1.x, p1.y),
                                    fh2(p0.z, p0.w), fh2(p1.z, p1.w));
            }
            lb[0] = *(const uint4*)(gB + kt + c0 * 8);
            lb[1] = *(const uint4*)(gB + kt + (c0 + 2) * 8);
        }

        const __half* pA = sg + buf * GTW;
        const __half* pB = sg + 2 * GTW + buf * GTW;
#pragma unroll
        for (int s = 0; s < 2; s++) {
            uint32_t a[4][4], b[4][2];
#pragma unroll
            for (int i = 0; i < 4; i++) {
                int rw = wm * 64 + i * 16 + g;
                uint2 lo = *(const uint2*)(pA + rw * GSH + s * 16 + 4 * t);
                uint2 hi = *(const uint2*)(pA + (rw + 8) * GSH + s * 16 + 4 * t);
                a[i][0] = lo.x;
                a[i][1] = hi.x;
                a[i][2] = lo.y;
                a[i][3] = hi.y;
            }
#pragma unroll
            for (int j = 0; j < 4; j++) {
                int rn = wn * 32 + j * 8 + g;
                uint2 bb = *(const uint2*)(pB + rn * GSH + s * 16 + 4 * t);
                b[j][0] = bb.x;
                b[j][1] = bb.y;
            }
#pragma unroll
            for (int i = 0; i < 4; i++)
#pragma unroll
                for (int j = 0; j < 4; j++) mma16(d[i][j], a[i], b[j]);
        }

        if (more) {
            uint4* qA = (uint4*)(sg + (buf ^ 1) * GTW + aRow * GSH);
            uint4* qB = (uint4*)(sg + 2 * GTW + (buf ^ 1) * GTW + aRow * GSH);
            qA[c0] = la[0];
            qA[c0 + 2] = la[1];
            qB[c0] = lb[0];
            qB[c0 + 2] = lb[1];
        }
        buf ^= 1;
        __syncthreads();
    }

#pragma unroll
    for (int i = 0; i < 4; i++) {
        int r0 = m0 + wm * 64 + i * 16 + g;
#pragma unroll
        for (int j = 0; j < 4; j++) {
            int colh = n0 + (wn * 2 + (j >> 1)) * 16 + 4 * t + 2 * (j & 1);
            *(uint32_t*)(C + (size_t)r0 * N + colh) = fh2(d[i][j][0], d[i][j][1]);
            *(uint32_t*)(C + (size_t)(r0 + 8) * N + colh) =
                fh2(d[i][j][2], d[i][j][3]);
        }
    }
}

// output projection: A = g_hh (half permuted), B = g_Woh, C fp32
__global__ __launch_bounds__(256, 2) void gemm_out(float* __restrict__ C) {
    extern __shared__ __half sg[];
    const __half* A = g_hh;
    const __half* B = g_Woh;
    const int M = BB * SS, N = DM, K = DM;

    const int tid = threadIdx.x;
    const int lane = tid & 31;
    const int wid = tid >> 5;
    const int g = lane >> 2;
    const int t = lane & 3;
    const int wm = wid & 1;
    const int wn = wid >> 1;
    const int m0 = blockIdx.y * 128;
    const int n0 = blockIdx.x * 128;

    const int aRow = tid >> 1;
    const int c0 = tid & 1;

    const __half* gA = A + (size_t)(m0 + aRow) * K;
    const __half* gB = B + (size_t)(n0 + aRow) * K;

    float d[4][4][4];
#pragma unroll
    for (int i = 0; i < 4; i++)
#pragma unroll
        for (int j = 0; j < 4; j++)
#pragma unroll
            for (int c = 0; c < 4; c++) d[i][j][c] = 0.f;

    uint4 la[2], lb[2];
    la[0] = *(const uint4*)(gA + c0 * 8);
    la[1] = *(const uint4*)(gA + (c0 + 2) * 8);
    lb[0] = *(const uint4*)(gB + c0 * 8);
    lb[1] = *(const uint4*)(gB + (c0 + 2) * 8);
    {
        uint4* sA = (uint4*)(sg + aRow * GSH);
        uint4* sB = (uint4*)(sg + 2 * GTW + aRow * GSH);
        sA[c0] = la[0];
        sA[c0 + 2] = la[1];
        sB[c0] = lb[0];
        sB[c0 + 2] = lb[1];
    }
    __syncthreads();

    int buf = 0;
    for (int kt = 32; kt <= K; kt += 32) {
        const bool more = (kt < K);
        if (more) {
            la[0] = *(const uint4*)(gA + kt + c0 * 8);
            la[1] = *(const uint4*)(gA + kt + (c0 + 2) * 8);
            lb[0] = *(const uint4*)(gB + kt + c0 * 8);
            lb[1] = *(const uint4*)(gB + kt + (c0 + 2) * 8);
        }

        const __half* pA = sg + buf * GTW;
        const __half* pB = sg + 2 * GTW + buf * GTW;
#pragma unroll
        for (int s = 0; s < 2; s++) {
            uint32_t a[4][4], b[4][2];
#pragma unroll
            for (int i = 0; i < 4; i++) {
                int rw = wm * 64 + i * 16 + g;
                uint2 lo = *(const uint2*)(pA + rw * GSH + s * 16 + 4 * t);
                uint2 hi = *(const uint2*)(pA + (rw + 8) * GSH + s * 16 + 4 * t);
                a[i][0] = lo.x;
                a[i][1] = hi.x;
                a[i][2] = lo.y;
                a[i][3] = hi.y;
            }
#pragma unroll
            for (int j = 0; j < 4; j++) {
                int rn = wn * 32 + j * 8 + g;
                uint2 bb = *(const uint2*)(pB + rn * GSH + s * 16 + 4 * t);
                b[j][0] = bb.x;
                b[j][1] = bb.y;
            }
#pragma unroll
            for (int i = 0; i < 4; i++)
#pragma unroll
                for (int j = 0; j < 4; j++) mma16(d[i][j], a[i], b[j]);
        }

        if (more) {
            uint4* qA = (uint4*)(sg + (buf ^ 1) * GTW + aRow * GSH);
            uint4* qB = (uint4*)(sg + 2 * GTW + (buf ^ 1) * GTW + aRow * GSH);
            qA[c0] = la[0];
            qA[c0 + 2] = la[1];
            qB[c0] = lb[0];
            qB[c0 + 2] = lb[1];
        }
        buf ^= 1;
        __syncthreads();
    }

#pragma unroll
    for (int i = 0; i < 4; i++) {
        int r0 = m0 + wm * 64 + i * 16 + g;
#pragma unroll
        for (int j = 0; j < 4; j++) {
            int cn = n0 + wn * 32 + j * 8 + t * 2;
            *(float2*)(C + (size_t)r0 * N + cn) = make_float2(d[i][j][0], d[i][j][1]);
            *(float2*)(C + (size_t)(r0 + 8) * N + cn) =
                make_float2(d[i][j][2], d[i][j][3]);
        }
    }
}

// ---------------------------------------------------------------- flash (fp16)
// CTA = (b, h, 128 query rows), 128 threads / 4 warps, warp owns 32 rows.
// l computed via an extra "ones" B-tile in the P@V mma (j==8): no sum
// reduction, no shuffles for l; rescale folds in automatically.
#define KSH 80
#define VSH 144
#define KS_HALVES (128 * KSH)
#define FL_SMEM ((128 * KSH + 64 * VSH) * 2)
#define ONES2 0x3C003C00u

__global__ __launch_bounds__(128, 3) void flash_h(const __half* __restrict__ qp,
                                                  const __half* __restrict__ kp,
                                                  const __half* __restrict__ vp,
                                                  __half* __restrict__ op) {
    extern __shared__ __half sm[];
    __half* Ks = sm;
    __half* Vt = sm + KS_HALVES;

    const int tid = threadIdx.x;
    const int lane = tid & 31;
    const int wid = tid >> 5;
    const int g = lane >> 2;
    const int t = lane & 3;
    const int b = blockIdx.z;
    const int h = blockIdx.y;
    const int s0 = blockIdx.x * 128;
    const int rowbase = wid * 32;

    const __half* gq = qp + ((size_t)(b * SS + s0) * HH + h) * DQ;
    uint32_t qa[2][4][4];
#pragma unroll
    for (int i = 0; i < 2; i++) {
        const __half* q0 = gq + (size_t)(rowbase + 16 * i + g) * DM;
        const __half* q1 = q0 + 8 * DM;
#pragma unroll
        for (int s = 0; s < 4; s++) {
            uint2 u0 = *(const uint2*)(q0 + s * 16 + 4 * t);
            uint2 u1 = *(const uint2*)(q1 + s * 16 + 4 * t);
            qa[i][s][0] = u0.x;
            qa[i][s][1] = u1.x;
            qa[i][s][2] = u0.y;
            qa[i][s][3] = u1.y;
        }
    }

    float m[4];
#pragma unroll
    for (int r = 0; r < 4; r++) m[r] = -INFINITY;
    // o[i][0..7] = output tiles, o[i][8] = row-sum tile (l)
    float o[2][9][4];
#pragma unroll
    for (int i = 0; i < 2; i++)
#pragma unroll
        for (int j = 0; j < 9; j++)
#pragma unroll
            for (int c = 0; c < 4; c++) o[i][j][c] = 0.f;

    for (int t0 = 0; t0 < SS; t0 += 128) {
        __syncthreads();

        if (tid < 64) {
            const __half* v0 = vp + ((size_t)(b * SS + t0 + 2 * tid) * HH + h) * DQ;
            const __half* v1 = v0 + DM;
            int grp = tid >> 3, p = tid & 7;
            int colh = grp * 16 + ((p & 3) * 2 + (p >> 2)) * 2;
#pragma unroll
            for (int c = 0; c < 8; c++) {
                uint4 ua = *(const uint4*)(v0 + c * 8);
                uint4 ub = *(const uint4*)(v1 + c * 8);
                const __half* ah = (const __half*)&ua;
                const __half* bh = (const __half*)&ub;
#pragma unroll
                for (int mm = 0; mm < 8; mm++) {
                    *(__half2*)(Vt + (size_t)(c * 8 + mm) * VSH + colh) =
                        __halves2half2(ah[mm], bh[mm]);
                }
            }
        } else {
            int j = tid - 64;
            const __half* k0 = kp + ((size_t)(b * SS + t0 + 2 * j) * HH + h) * DQ;
#pragma unroll
            for (int r2 = 0; r2 < 2; r2++) {
                const uint4* src = (const uint4*)(k0 + r2 * DM);
                uint4* dst = (uint4*)(Ks + (size_t)(2 * j + r2) * KSH);
#pragma unroll
                for (int mm = 0; mm < 8; mm++) {
                    int c = (mm + j) & 7;
                    dst[c] = src[c];
                }
            }
        }
        __syncthreads();

#pragma unroll
        for (int chunk = 0; chunk < 4; chunk++) {
            const int kb = chunk * 32;

            float sj[2][4][4];
#pragma unroll
            for (int i = 0; i < 2; i++)
#pragma unroll
                for (int j = 0; j < 4; j++)
#pragma unroll
                    for (int c = 0; c < 4; c++) sj[i][j][c] = 0.f;

#pragma unroll
            for (int s = 0; s < 4; s++) {
#pragma unroll
                for (int j = 0; j < 4; j++) {
                    uint2 bb = *(const uint2*)(Ks + (size_t)(kb + j * 8 + g) * KSH +
                                               s * 16 + 4 * t);
                    uint32_t bf[2] = {bb.x, bb.y};
                    mma16(sj[0][j], qa[0][s], bf);
                    mma16(sj[1][j], qa[1][s], bf);
                }
            }

            // online softmax (base 2; scale folded into Q)
            float mx[4] = {-INFINITY, -INFINITY, -INFINITY, -INFINITY};
#pragma unroll
            for (int i = 0; i < 2; i++)
#pragma unroll
                for (int j = 0; j < 4; j++) {
                    mx[2 * i + 0] = fmaxf(mx[2 * i + 0], fmaxf(sj[i][j][0], sj[i][j][1]));
                    mx[2 * i + 1] = fmaxf(mx[2 * i + 1], fmaxf(sj[i][j][2], sj[i][j][3]));
                }
            float al[4];
#pragma unroll
            for (int r = 0; r < 4; r++) {
                mx[r] = fmaxf(mx[r], __shfl_xor_sync(0xffffffffu, mx[r], 1));
                mx[r] = fmaxf(mx[r], __shfl_xor_sync(0xffffffffu, mx[r], 2));
                float mn = fmaxf(m[r], mx[r]);
                al[r] = ex2f(m[r] - mn);
                m[r] = mn;
            }
#pragma unroll
            for (int i = 0; i < 2; i++)
#pragma unroll
                for (int j = 0; j < 4; j++) {
                    sj[i][j][0] = ex2f(sj[i][j][0] - m[2 * i + 0]);
                    sj[i][j][1] = ex2f(sj[i][j][1] - m[2 * i + 0]);
                    sj[i][j][2] = ex2f(sj[i][j][2] - m[2 * i + 1]);
                    sj[i][j][3] = ex2f(sj[i][j][3] - m[2 * i + 1]);
                }
            // rescale all tiles incl. the l tile (j==8)
#pragma unroll
            for (int i = 0; i < 2; i++)
#pragma unroll
                for (int j = 0; j < 9; j++) {
                    o[i][j][0] *= al[2 * i + 0];
                    o[i][j][1] *= al[2 * i + 0];
                    o[i][j][2] *= al[2 * i + 1];
                    o[i][j][3] *= al[2 * i + 1];
                }

            // O += P @ V  ;  l += P @ 1 (j==8, constant ones fragment)
#pragma unroll
            for (int G = 0; G < 2; G++) {
                uint32_t pa[2][4];
#pragma unroll
                for (int i = 0; i < 2; i++) {
                    pa[i][0] = fh2(sj[i][2 * G][0], sj[i][2 * G][1]);
                    pa[i][1] = fh2(sj[i][2 * G][2], sj[i][2 * G][3]);
                    pa[i][2] = fh2(sj[i][2 * G + 1][0], sj[i][2 * G + 1][1]);
                    pa[i][3] = fh2(sj[i][2 * G + 1][2], sj[i][2 * G + 1][3]);
                }
                int kg = chunk * 2 + G;
#pragma unroll
                for (int j = 0; j < 8; j++) {
                    uint2 bb = *(const uint2*)(Vt + (size_t)(j * 8 + g) * VSH +
                                               kg * 16 + 4 * t);
                    uint32_t bf[2] = {bb.x, bb.y};
                    mma16(o[0][j], pa[0], bf);
                    mma16(o[1][j], pa[1], bf);
                }
                uint32_t ones[2] = {ONES2, ONES2};
                mma16(o[0][8], pa[0], ones);
                mma16(o[1][8], pa[1], ones);
            }
        }
    }

    // normalize + store heads (half, phys layout matches final-GEMM perm)
    __half* ob = op + ((size_t)(b * HH + h) * SS + s0) * DQ;
#pragma unroll
    for (int i = 0; i < 2; i++) {
        int rA = rowbase + 16 * i + g;
        float inv0 = 1.f / o[i][8][0];
        float inv1 = 1.f / o[i][8][2];
#pragma unroll
        for (int j = 0; j < 8; j++) {
            int cn = j * 8 + t * 2;
            *(uint32_t*)(ob + (size_t)rA * DQ + cn) =
                fh2(o[i][j][0] * inv0, o[i][j][1] * inv0);
            *(uint32_t*)(ob + (size_t)(rA + 8) * DQ + cn) =
                fh2(o[i][j][2] * inv1, o[i][j][3] * inv1);
        }
    }
}

// ---------------------------------------------------------------- launch
extern "C" void kernel_launch(void* const* d_in, const int* in_sizes, int n_in,
                              void* d_out, int out_size) {
    const float* xq = (const float*)d_in[0];
    const float* xk = (const float*)d_in[1];
    const float* xv = (const float*)d_in[2];
    const float* Qw = (const float*)d_in[3];
    const float* Kw = (const float*)d_in[4];
    const float* Vw = (const float*)d_in[5];
    const float* Wo = (const float*)d_in[6];
    float* out = (float*)d_out;

    __half *pq, *pk, *pv, *ph;
    cudaGetSymbolAddress((void**)&pq, g_qh);
    cudaGetSymbolAddress((void**)&pk, g_kh);
    cudaGetSymbolAddress((void**)&pv, g_vh);
    cudaGetSymbolAddress((void**)&ph, g_hh);

    static int attr_done = 0;
    if (!attr_done) {
        cudaFuncSetAttribute(gemm_qkv, cudaFuncAttributeMaxDynamicSharedMemorySize,
                             GE_SMEM);
        cudaFuncSetAttribute(gemm_out, cudaFuncAttributeMaxDynamicSharedMemorySize,
                             GE_SMEM);
        cudaFuncSetAttribute(flash_h, cudaFuncAttributeMaxDynamicSharedMemorySize,
                             FL_SMEM);
        attr_done = 1;
    }

    prep_w<<<64, 256>>>(Qw, Kw, Vw, Wo);

    gemm_qkv<<<dim3(DM / 128, (BB * SS) / 128, 3), 256, GE_SMEM>>>(xq, xk, xv);

    flash_h<<<dim3(SS / 128, HH, BB), 128, FL_SMEM>>>(pq, pk, pv, ph);

    gemm_out<<<dim3(DM / 128, (BB * SS) / 128), 256, GE_SMEM>>>(out);
}